// round 3
// baseline (speedup 1.0000x reference)
#include <cuda_runtime.h>
#include <cstdint>
#include <cstddef>

// ---------------- problem constants ----------------
#define B_   2
#define N_   1569
#define C_   768
#define H_   12
#define D_   64
#define P_   196
#define F_   8
#define S_   1568          // F_*P_ = N_-1
#define C3_  2304          // 3*C_
#define SCALE 0.125f       // d^-0.5 = 1/8

// ---------------- scratch (device globals; no allocation allowed) ----------------
__device__ float g_qkv  [B_*N_*C3_];     //  7,229,952  (B*N, 3C) row-major
__device__ float g_traj [B_*S_*F_*C_];   // 19,267,584  (B,S,F,C)
__device__ float g_xdiag[B_*S_*C_];      //  2,408,448  (B*S, C)
__device__ float g_q2   [B_*S_*C_];      //  2,408,448  (B*S, C)  (scale folded in)
__device__ float g_k2   [B_*S_*F_*C_];   // 19,267,584  (B,S,F,C)
__device__ float g_attin[B_*N_*C_];      //  2,411,520  (B*N, C)  concat(cls_out, out_pre)

// ======================================================================
// Generic fp32 SGEMM: C[M,N] = alpha * A[M,K] @ B[K,N] (+ bias)
// BM=BN=128, BK=8, 256 threads, 8x8 per-thread tile.
// N and K must be multiples of 128 / 8 respectively (true for all calls).
// ======================================================================
__global__ __launch_bounds__(256) void sgemm_k(
    const float* __restrict__ A, int lda,
    const float* __restrict__ Bw, int ldb,
    float* __restrict__ Cc, int ldc,
    int M, int Nn, int K, float alpha, const float* __restrict__ bias)
{
    __shared__ float As[8][132];   // padded: row stride 132 floats (16B-divisible)
    __shared__ float Bs[8][128];

    const int tid  = threadIdx.x;
    const int tx   = tid & 15;
    const int ty   = tid >> 4;
    const int row0 = blockIdx.y * 128;
    const int col0 = blockIdx.x * 128;

    const int a_m = tid >> 1;          // 0..127
    const int a_k = (tid & 1) * 4;     // 0 or 4
    const int b_k = tid >> 5;          // 0..7
    const int b_n = (tid & 31) * 4;    // 0..124

    float acc[8][8];
    #pragma unroll
    for (int i = 0; i < 8; i++)
        #pragma unroll
        for (int j = 0; j < 8; j++) acc[i][j] = 0.f;

    for (int k0 = 0; k0 < K; k0 += 8) {
        float4 av = make_float4(0.f, 0.f, 0.f, 0.f);
        if (row0 + a_m < M)
            av = *(const float4*)(A + (size_t)(row0 + a_m) * lda + (k0 + a_k));
        As[a_k + 0][a_m] = av.x;
        As[a_k + 1][a_m] = av.y;
        As[a_k + 2][a_m] = av.z;
        As[a_k + 3][a_m] = av.w;
        *(float4*)&Bs[b_k][b_n] =
            *(const float4*)(Bw + (size_t)(k0 + b_k) * ldb + (col0 + b_n));
        __syncthreads();

        #pragma unroll
        for (int kk = 0; kk < 8; kk++) {
            float ra[8], rb[8];
            *(float4*)&ra[0] = *(const float4*)&As[kk][ty * 8];
            *(float4*)&ra[4] = *(const float4*)&As[kk][ty * 8 + 4];
            *(float4*)&rb[0] = *(const float4*)&Bs[kk][tx * 8];
            *(float4*)&rb[4] = *(const float4*)&Bs[kk][tx * 8 + 4];
            #pragma unroll
            for (int i = 0; i < 8; i++)
                #pragma unroll
                for (int j = 0; j < 8; j++)
                    acc[i][j] += ra[i] * rb[j];
        }
        __syncthreads();
    }

    float bv[8];
    if (bias) {
        #pragma unroll
        for (int j = 0; j < 8; j++) bv[j] = bias[col0 + tx * 8 + j];
    } else {
        #pragma unroll
        for (int j = 0; j < 8; j++) bv[j] = 0.f;
    }
    #pragma unroll
    for (int i = 0; i < 8; i++) {
        int r = row0 + ty * 8 + i;
        if (r < M) {
            float* crow = Cc + (size_t)r * ldc + col0 + tx * 8;
            #pragma unroll
            for (int j = 0; j < 8; j++)
                crow[j] = acc[i][j] * alpha + bv[j];
        }
    }
}

// ======================================================================
// CLS attention: one block per (b, head). Softmax over all N keys.
// Writes g_attin row 0 of each batch.
// ======================================================================
__global__ __launch_bounds__(256) void cls_attn_kernel()
{
    __shared__ float sims[N_];
    __shared__ float q0s[64];
    __shared__ float red[9];

    const int bh   = blockIdx.x;
    const int b    = bh / H_;
    const int head = bh % H_;
    const int tid  = threadIdx.x;
    const int w    = tid >> 5;
    const int lane = tid & 31;

    const float* base = g_qkv + (size_t)b * N_ * C3_;

    if (tid < 64) q0s[tid] = base[head * D_ + tid];
    __syncthreads();

    for (int j = tid; j < N_; j += 256) {
        const float* kr = base + (size_t)j * C3_ + C_ + head * D_;
        float dsum = 0.f;
        #pragma unroll
        for (int di = 0; di < 64; di += 4) {
            float4 kv = *(const float4*)(kr + di);
            dsum += q0s[di] * kv.x + q0s[di + 1] * kv.y
                  + q0s[di + 2] * kv.z + q0s[di + 3] * kv.w;
        }
        sims[j] = dsum * SCALE;
    }
    __syncthreads();

    // block max
    float m = -1e30f;
    for (int j = tid; j < N_; j += 256) m = fmaxf(m, sims[j]);
    #pragma unroll
    for (int off = 16; off; off >>= 1) m = fmaxf(m, __shfl_xor_sync(0xffffffffu, m, off));
    if (lane == 0) red[w] = m;
    __syncthreads();
    if (tid == 0) {
        float mm = red[0];
        #pragma unroll
        for (int i = 1; i < 8; i++) mm = fmaxf(mm, red[i]);
        red[8] = mm;
    }
    __syncthreads();
    const float M = red[8];
    __syncthreads();

    // exp + block sum
    float ls = 0.f;
    for (int j = tid; j < N_; j += 256) {
        float p = __expf(sims[j] - M);
        sims[j] = p;
        ls += p;
    }
    #pragma unroll
    for (int off = 16; off; off >>= 1) ls += __shfl_xor_sync(0xffffffffu, ls, off);
    if (lane == 0) red[w] = ls;
    __syncthreads();
    if (tid == 0) {
        float ss = 0.f;
        #pragma unroll
        for (int i = 0; i < 8; i++) ss += red[i];
        red[8] = ss;
    }
    __syncthreads();
    const float SUM = red[8];

    if (tid < 64) {
        float acc = 0.f;
        const float* vcol = base + 2 * C_ + head * D_ + tid;
        #pragma unroll 4
        for (int j = 0; j < N_; j++)
            acc += sims[j] * vcol[(size_t)j * C3_];
        g_attin[(size_t)b * N_ * C_ + head * D_ + tid] = acc / SUM;
    }
}

// ======================================================================
// Space attention -> trajectory.
// Block = (query-chunk of 196, frame f, bh). Loads K_f, V_f (196x64) to smem,
// each warp processes 4 queries at a time with register blocking.
// Output written directly in (B,S,F,C) layout (head-concat), so no transpose.
// smem layout (floats): Ks[0,14560) Vs[14560,29120) qs[29120,33216) ps[33216,45760)
// ======================================================================
#define SA_THREADS 512
#define SA_WARPS   16
#define SA_SMEM_FLOATS 45760
#define SA_SMEM_BYTES  (SA_SMEM_FLOATS * 4)

__global__ __launch_bounds__(SA_THREADS) void space_attn_kernel()
{
    extern __shared__ float sm[];
    float* Ks = sm;              // 224 rows x 65 (rows >=196 zeroed)
    float* Vs = sm + 14560;
    float* qs = sm + 29120;      // [16 warps][4 q][64]
    float* ps = sm + 33216;      // [16 warps][4 q][196]

    const int qc   = blockIdx.x;       // 0..7  (196 queries each)
    const int f    = blockIdx.y;
    const int bh   = blockIdx.z;
    const int b    = bh / H_;
    const int head = bh % H_;
    const int tid  = threadIdx.x;
    const int w    = tid >> 5;
    const int lane = tid & 31;

    const float* base = g_qkv + (size_t)b * N_ * C3_;

    // load K_f, V_f tiles (padded to 224 rows, zero-filled)
    for (int idx = tid; idx < 224 * 64; idx += SA_THREADS) {
        int j  = idx >> 6;
        int di = idx & 63;
        float kv = 0.f, vv = 0.f;
        if (j < P_) {
            const float* row = base + (size_t)(1 + f * P_ + j) * C3_ + head * D_;
            kv = row[C_ + di];
            vv = row[2 * C_ + di];
        }
        Ks[j * 65 + di] = kv;
        Vs[j * 65 + di] = vv;
    }
    __syncthreads();

    float* myqs = qs + w * 4 * 64;
    float* myps = ps + w * 4 * 196;

    for (int g = w; g < 49; g += SA_WARPS) {       // 49 groups of 4 queries
        const int sq0 = qc * P_ + g * 4;           // query index in [0,S)

        #pragma unroll
        for (int u = 0; u < 4; u++) {
            const float* qrow = base + (size_t)(1 + sq0 + u) * C3_ + head * D_;
            myqs[u * 64 + lane]      = qrow[lane];
            myqs[u * 64 + lane + 32] = qrow[lane + 32];
        }
        __syncwarp();

        float acc[4][7];
        #pragma unroll
        for (int u = 0; u < 4; u++)
            #pragma unroll
            for (int t = 0; t < 7; t++) acc[u][t] = 0.f;

        #pragma unroll 4
        for (int di = 0; di < 64; di++) {
            float q0 = myqs[di];
            float q1 = myqs[64 + di];
            float q2v = myqs[128 + di];
            float q3 = myqs[192 + di];
            #pragma unroll
            for (int t = 0; t < 7; t++) {
                float kvv = Ks[(lane + 32 * t) * 65 + di];
                acc[0][t] += q0  * kvv;
                acc[1][t] += q1  * kvv;
                acc[2][t] += q2v * kvv;
                acc[3][t] += q3  * kvv;
            }
        }

        float rinv[4];
        #pragma unroll
        for (int u = 0; u < 4; u++) {
            float m = -1e30f;
            #pragma unroll
            for (int t = 0; t < 7; t++) {
                int j = lane + 32 * t;
                if (j < P_) m = fmaxf(m, acc[u][t] * SCALE);
            }
            #pragma unroll
            for (int off = 16; off; off >>= 1)
                m = fmaxf(m, __shfl_xor_sync(0xffffffffu, m, off));
            float lsum = 0.f;
            #pragma unroll
            for (int t = 0; t < 7; t++) {
                int j = lane + 32 * t;
                if (j < P_) {
                    float p = __expf(acc[u][t] * SCALE - m);
                    myps[u * 196 + j] = p;
                    lsum += p;
                }
            }
            #pragma unroll
            for (int off = 16; off; off >>= 1)
                lsum += __shfl_xor_sync(0xffffffffu, lsum, off);
            rinv[u] = 1.f / lsum;
        }
        __syncwarp();

        float o[4][2];
        #pragma unroll
        for (int u = 0; u < 4; u++) { o[u][0] = 0.f; o[u][1] = 0.f; }
        #pragma unroll 2
        for (int j = 0; j < P_; j++) {
            float v0 = Vs[j * 65 + lane];
            float v1 = Vs[j * 65 + lane + 32];
            #pragma unroll
            for (int u = 0; u < 4; u++) {
                float p = myps[u * 196 + j];
                o[u][0] += p * v0;
                o[u][1] += p * v1;
            }
        }
        #pragma unroll
        for (int u = 0; u < 4; u++) {
            float* op = g_traj + ((size_t)(b * S_ + sq0 + u) * F_ + f) * C_ + head * D_;
            op[lane]      = o[u][0] * rinv[u];
            op[lane + 32] = o[u][1] * rinv[u];
        }
        __syncwarp();
    }
}

// ======================================================================
// x_diag gather: x_diag[b,s,c] = traj[b,s,s/P,c]
// ======================================================================
__global__ __launch_bounds__(256) void xdiag_kernel()
{
    int i = blockIdx.x * 256 + threadIdx.x;
    if (i >= B_ * S_ * C_) return;
    int c = i % C_;
    int r = i / C_;          // b*S + s
    int s = r % S_;
    g_xdiag[i] = g_traj[((size_t)r * F_ + (s / P_)) * C_ + c];
}

// ======================================================================
// Final frame attention: one warp per (b, head, s).
// logits_f = q2 . k2[f]  (scale already folded into q2)
// writes attn output (B,h,S,F) and out_pre rows of g_attin.
// ======================================================================
__global__ __launch_bounds__(256) void final_attn_kernel(float* __restrict__ attn_out)
{
    int gw   = (blockIdx.x * 256 + threadIdx.x) >> 5;
    int lane = threadIdx.x & 31;
    if (gw >= B_ * H_ * S_) return;
    int b    = gw / (H_ * S_);
    int r    = gw % (H_ * S_);
    int head = r / S_;
    int s    = r % S_;

    const float* q2p = g_q2 + ((size_t)b * S_ + s) * C_ + head * D_;
    float q0 = q2p[lane];
    float q1 = q2p[lane + 32];

    const float* k2p = g_k2 + ((size_t)b * S_ + s) * (size_t)F_ * C_ + head * D_;
    float lg[8];
    #pragma unroll
    for (int f = 0; f < 8; f++) {
        float t = q0 * k2p[f * C_ + lane] + q1 * k2p[f * C_ + lane + 32];
        #pragma unroll
        for (int off = 16; off; off >>= 1)
            t += __shfl_xor_sync(0xffffffffu, t, off);
        lg[f] = t;
    }
    float m = lg[0];
    #pragma unroll
    for (int f = 1; f < 8; f++) m = fmaxf(m, lg[f]);
    float p[8], sum = 0.f;
    #pragma unroll
    for (int f = 0; f < 8; f++) { p[f] = __expf(lg[f] - m); sum += p[f]; }
    float inv = 1.f / sum;

    float* ap = attn_out + (((size_t)b * H_ + head) * S_ + s) * F_;
    #pragma unroll
    for (int f = 0; f < 8; f++)
        if (lane == f) ap[f] = p[f] * inv;

    const float* tp = g_traj + ((size_t)b * S_ + s) * (size_t)F_ * C_ + head * D_;
    float o0 = 0.f, o1 = 0.f;
    #pragma unroll
    for (int f = 0; f < 8; f++) {
        float pf = p[f] * inv;
        o0 += pf * tp[f * C_ + lane];
        o1 += pf * tp[f * C_ + lane + 32];
    }
    float* op = g_attin + ((size_t)b * N_ + 1 + s) * C_ + head * D_;
    op[lane]      = o0;
    op[lane + 32] = o1;
}

// ======================================================================
// Host launcher
// ======================================================================
extern "C" void kernel_launch(void* const* d_in, const int* in_sizes, int n_in,
                              void* d_out, int out_size)
{
    const float* x      = (const float*)d_in[0];
    const float* W_qkv  = (const float*)d_in[1];
    const float* W_pq   = (const float*)d_in[2];
    const float* W_pkv  = (const float*)d_in[3];
    const float* W_proj = (const float*)d_in[4];
    const float* b_proj = (const float*)d_in[5];
    // d_in[6], d_in[7]: seq_len / num_frames (compile-time constants here)

    float* out  = (float*)d_out;
    float* attn = out + (size_t)B_ * N_ * C_;

    float *qkv, *traj, *xdiag, *q2, *k2, *attin;
    cudaGetSymbolAddress((void**)&qkv,   g_qkv);
    cudaGetSymbolAddress((void**)&traj,  g_traj);
    cudaGetSymbolAddress((void**)&xdiag, g_xdiag);
    cudaGetSymbolAddress((void**)&q2,    g_q2);
    cudaGetSymbolAddress((void**)&k2,    g_k2);
    cudaGetSymbolAddress((void**)&attin, g_attin);

    // 1) qkv = x @ W_qkv      (3138 x 2304 x 768)
    sgemm_k<<<dim3(C3_ / 128, (B_ * N_ + 127) / 128), 256>>>(
        x, C_, W_qkv, C3_, qkv, C3_, B_ * N_, C3_, C_, 1.f, nullptr);

    // 2) cls attention -> g_attin rows 0
    cls_attn_kernel<<<B_ * H_, 256>>>();

    // 3) space attention -> g_traj (B,S,F,C)
    cudaFuncSetAttribute(space_attn_kernel,
                         cudaFuncAttributeMaxDynamicSharedMemorySize, SA_SMEM_BYTES);
    space_attn_kernel<<<dim3(8, F_, B_ * H_), SA_THREADS, SA_SMEM_BYTES>>>();

    // 4) x_diag gather
    xdiag_kernel<<<(B_ * S_ * C_) / 256, 256>>>();

    // 5) q2 = scale * (x_diag @ W_pq)    (3136 x 768 x 768)
    sgemm_k<<<dim3(C_ / 128, (B_ * S_ + 127) / 128), 256>>>(
        xdiag, C_, W_pq, C_, q2, C_, B_ * S_, C_, C_, SCALE, nullptr);

    // 6) k2 = traj @ W_pkv[:, :C]        (25088 x 768 x 768)   [v2 is dead code]
    sgemm_k<<<dim3(C_ / 128, (B_ * S_ * F_) / 128), 256>>>(
        traj, C_, W_pkv, 2 * C_, k2, C_, B_ * S_ * F_, C_, C_, 1.f, nullptr);

    // 7) frame softmax + weighted traj sum -> attn output + g_attin rows 1..
    final_attn_kernel<<<(B_ * H_ * S_ * 32) / 256, 256>>>(attn);

    // 8) out = concat(cls, out_pre) @ W_proj + b_proj -> d_out
    sgemm_k<<<dim3(C_ / 128, (B_ * N_ + 127) / 128), 256>>>(
        attin, C_, W_proj, C_, out, C_, B_ * N_, C_, C_, 1.f, b_proj);
}

// round 6
// speedup vs baseline: 1.7412x; 1.7412x over previous
#include <cuda_runtime.h>
#include <cstdint>
#include <cstddef>

// ---------------- problem constants ----------------
#define B_   2
#define N_   1569
#define C_   768
#define H_   12
#define D_   64
#define P_   196
#define F_   8
#define S_   1568          // F_*P_ = N_-1
#define C3_  2304          // 3*C_
#define SCALE 0.125f       // d^-0.5 = 1/8

// ---------------- scratch (device globals; no allocation allowed) ----------------
__device__ float g_qkv  [B_*N_*C3_];     //  (B*N, 3C) row-major
__device__ float g_traj [B_*S_*F_*C_];   //  (B,S,F,C)
__device__ float g_xdiag[B_*S_*C_];      //  (B*S, C)
__device__ float g_q2   [B_*S_*C_];      //  (B*S, C)  (scale folded in)
__device__ float g_k2   [B_*S_*F_*C_];   //  (B,S,F,C)
__device__ float g_attin[B_*N_*C_];      //  (B*N, C)  concat(cls_out, out_pre)

// ======================================================================
// TF32 tensor-core GEMM: C[M,N] = alpha * A[M,K] @ B[K,N] (+ bias)
// BM=BN=128, BK=32, 256 threads (8 warps), warp tile 64x32 via
// mma.sync.aligned.m16n8k8.row.col.f32.tf32.tf32.f32.
// Requires: N % 128 == 0, K % 32 == 0 (true for all calls). M guarded.
// Smem: As[128][36] (bank = 4g+t, conflict-free), Bs[32][136] (bank = 8t+g).
// ======================================================================
__device__ __forceinline__ uint32_t f2tf32(float f) {
    uint32_t o;
    asm("cvt.rna.tf32.f32 %0, %1;" : "=r"(o) : "f"(f));
    return o;
}

__global__ __launch_bounds__(256) void gemm_tf32_k(
    const float* __restrict__ A, int lda,
    const float* __restrict__ Bw, int ldb,
    float* __restrict__ Cc, int ldc,
    int M, int K, float alpha, const float* __restrict__ bias)
{
    __shared__ uint32_t As[128 * 36];   // [row][k], stride 36
    __shared__ uint32_t Bs[32 * 136];   // [k][col], stride 136

    const int tid    = threadIdx.x;
    const int warp   = tid >> 5;
    const int lane   = tid & 31;
    const int g      = lane >> 2;       // group id 0..7
    const int t      = lane & 3;        // thread-in-group 0..3
    const int warp_m = warp >> 2;       // 0..1  -> 64-row slab
    const int warp_n = warp & 3;        // 0..3  -> 32-col slab
    const int row0   = blockIdx.y * 128;
    const int col0   = blockIdx.x * 128;

    float acc[4][4][4];
    #pragma unroll
    for (int mt = 0; mt < 4; mt++)
        #pragma unroll
        for (int nt = 0; nt < 4; nt++)
            #pragma unroll
            for (int r = 0; r < 4; r++) acc[mt][nt][r] = 0.f;

    for (int k0 = 0; k0 < K; k0 += 32) {
        // --- load A tile: 128x32 floats = 1024 float4, 4 per thread ---
        #pragma unroll
        for (int i = 0; i < 4; i++) {
            int idx = tid + i * 256;
            int r   = idx >> 3;          // 0..127
            int c   = (idx & 7) * 4;     // 0..28
            float4 av = make_float4(0.f, 0.f, 0.f, 0.f);
            if (row0 + r < M)
                av = *(const float4*)(A + (size_t)(row0 + r) * lda + k0 + c);
            uint32_t* dst = &As[r * 36 + c];
            dst[0] = f2tf32(av.x); dst[1] = f2tf32(av.y);
            dst[2] = f2tf32(av.z); dst[3] = f2tf32(av.w);
        }
        // --- load B tile: 32x128 floats = 1024 float4, 4 per thread ---
        #pragma unroll
        for (int i = 0; i < 4; i++) {
            int idx = tid + i * 256;
            int r   = idx >> 5;          // k-row 0..31
            int c   = (idx & 31) * 4;    // 0..124
            float4 bv = *(const float4*)(Bw + (size_t)(k0 + r) * ldb + col0 + c);
            uint32_t* dst = &Bs[r * 136 + c];
            dst[0] = f2tf32(bv.x); dst[1] = f2tf32(bv.y);
            dst[2] = f2tf32(bv.z); dst[3] = f2tf32(bv.w);
        }
        __syncthreads();

        #pragma unroll
        for (int kk = 0; kk < 32; kk += 8) {
            uint32_t a[4][4], bf[4][2];
            #pragma unroll
            for (int mt = 0; mt < 4; mt++) {
                int r = warp_m * 64 + mt * 16 + g;
                const uint32_t* p = &As[r * 36 + kk + t];
                a[mt][0] = p[0];
                a[mt][1] = p[8 * 36];
                a[mt][2] = p[4];
                a[mt][3] = p[8 * 36 + 4];
            }
            #pragma unroll
            for (int nt = 0; nt < 4; nt++) {
                int c = warp_n * 32 + nt * 8 + g;
                const uint32_t* p = &Bs[(kk + t) * 136 + c];
                bf[nt][0] = p[0];
                bf[nt][1] = p[4 * 136];
            }
            #pragma unroll
            for (int mt = 0; mt < 4; mt++)
                #pragma unroll
                for (int nt = 0; nt < 4; nt++) {
                    asm volatile(
                        "mma.sync.aligned.m16n8k8.row.col.f32.tf32.tf32.f32 "
                        "{%0,%1,%2,%3}, {%4,%5,%6,%7}, {%8,%9}, {%0,%1,%2,%3};"
                        : "+f"(acc[mt][nt][0]), "+f"(acc[mt][nt][1]),
                          "+f"(acc[mt][nt][2]), "+f"(acc[mt][nt][3])
                        : "r"(a[mt][0]), "r"(a[mt][1]), "r"(a[mt][2]), "r"(a[mt][3]),
                          "r"(bf[nt][0]), "r"(bf[nt][1]));
                }
        }
        __syncthreads();
    }

    // --- epilogue: alpha * acc + bias ---
    #pragma unroll
    for (int nt = 0; nt < 4; nt++) {
        int c = col0 + warp_n * 32 + nt * 8 + t * 2;
        float b0 = bias ? bias[c]     : 0.f;
        float b1 = bias ? bias[c + 1] : 0.f;
        #pragma unroll
        for (int mt = 0; mt < 4; mt++) {
            int r = row0 + warp_m * 64 + mt * 16 + g;
            if (r < M) {
                float* cp = Cc + (size_t)r * ldc + c;
                cp[0] = acc[mt][nt][0] * alpha + b0;
                cp[1] = acc[mt][nt][1] * alpha + b1;
            }
            if (r + 8 < M) {
                float* cp = Cc + (size_t)(r + 8) * ldc + c;
                cp[0] = acc[mt][nt][2] * alpha + b0;
                cp[1] = acc[mt][nt][3] * alpha + b1;
            }
        }
    }
}

// ======================================================================
// CLS attention: one block per (b, head). Softmax over all N keys.
// ======================================================================
__global__ __launch_bounds__(256) void cls_attn_kernel()
{
    __shared__ float sims[N_];
    __shared__ float q0s[64];
    __shared__ float red[9];

    const int bh   = blockIdx.x;
    const int b    = bh / H_;
    const int head = bh % H_;
    const int tid  = threadIdx.x;
    const int w    = tid >> 5;
    const int lane = tid & 31;

    const float* base = g_qkv + (size_t)b * N_ * C3_;

    if (tid < 64) q0s[tid] = base[head * D_ + tid];
    __syncthreads();

    for (int j = tid; j < N_; j += 256) {
        const float* kr = base + (size_t)j * C3_ + C_ + head * D_;
        float dsum = 0.f;
        #pragma unroll
        for (int di = 0; di < 64; di += 4) {
            float4 kv = *(const float4*)(kr + di);
            dsum += q0s[di] * kv.x + q0s[di + 1] * kv.y
                  + q0s[di + 2] * kv.z + q0s[di + 3] * kv.w;
        }
        sims[j] = dsum * SCALE;
    }
    __syncthreads();

    float m = -1e30f;
    for (int j = tid; j < N_; j += 256) m = fmaxf(m, sims[j]);
    #pragma unroll
    for (int off = 16; off; off >>= 1) m = fmaxf(m, __shfl_xor_sync(0xffffffffu, m, off));
    if (lane == 0) red[w] = m;
    __syncthreads();
    if (tid == 0) {
        float mm = red[0];
        #pragma unroll
        for (int i = 1; i < 8; i++) mm = fmaxf(mm, red[i]);
        red[8] = mm;
    }
    __syncthreads();
    const float M = red[8];
    __syncthreads();

    float ls = 0.f;
    for (int j = tid; j < N_; j += 256) {
        float p = __expf(sims[j] - M);
        sims[j] = p;
        ls += p;
    }
    #pragma unroll
    for (int off = 16; off; off >>= 1) ls += __shfl_xor_sync(0xffffffffu, ls, off);
    if (lane == 0) red[w] = ls;
    __syncthreads();
    if (tid == 0) {
        float ss = 0.f;
        #pragma unroll
        for (int i = 0; i < 8; i++) ss += red[i];
        red[8] = ss;
    }
    __syncthreads();
    const float SUM = red[8];

    if (tid < 64) {
        float acc = 0.f;
        const float* vcol = base + 2 * C_ + head * D_ + tid;
        #pragma unroll 4
        for (int j = 0; j < N_; j++)
            acc += sims[j] * vcol[(size_t)j * C3_];
        g_attin[(size_t)b * N_ * C_ + head * D_ + tid] = acc / SUM;
    }
}

// ======================================================================
// Space attention -> trajectory (unchanged from R1).
// ======================================================================
#define SA_THREADS 512
#define SA_WARPS   16
#define SA_SMEM_FLOATS 45760
#define SA_SMEM_BYTES  (SA_SMEM_FLOATS * 4)

__global__ __launch_bounds__(SA_THREADS) void space_attn_kernel()
{
    extern __shared__ float sm[];
    float* Ks = sm;              // 224 rows x 65
    float* Vs = sm + 14560;
    float* qs = sm + 29120;      // [16 warps][4 q][64]
    float* ps = sm + 33216;      // [16 warps][4 q][196]

    const int qc   = blockIdx.x;
    const int f    = blockIdx.y;
    const int bh   = blockIdx.z;
    const int b    = bh / H_;
    const int head = bh % H_;
    const int tid  = threadIdx.x;
    const int w    = tid >> 5;
    const int lane = tid & 31;

    const float* base = g_qkv + (size_t)b * N_ * C3_;

    for (int idx = tid; idx < 224 * 64; idx += SA_THREADS) {
        int j  = idx >> 6;
        int di = idx & 63;
        float kv = 0.f, vv = 0.f;
        if (j < P_) {
            const float* row = base + (size_t)(1 + f * P_ + j) * C3_ + head * D_;
            kv = row[C_ + di];
            vv = row[2 * C_ + di];
        }
        Ks[j * 65 + di] = kv;
        Vs[j * 65 + di] = vv;
    }
    __syncthreads();

    float* myqs = qs + w * 4 * 64;
    float* myps = ps + w * 4 * 196;

    for (int gq = w; gq < 49; gq += SA_WARPS) {
        const int sq0 = qc * P_ + gq * 4;

        #pragma unroll
        for (int u = 0; u < 4; u++) {
            const float* qrow = base + (size_t)(1 + sq0 + u) * C3_ + head * D_;
            myqs[u * 64 + lane]      = qrow[lane];
            myqs[u * 64 + lane + 32] = qrow[lane + 32];
        }
        __syncwarp();

        float acc[4][7];
        #pragma unroll
        for (int u = 0; u < 4; u++)
            #pragma unroll
            for (int tt = 0; tt < 7; tt++) acc[u][tt] = 0.f;

        #pragma unroll 4
        for (int di = 0; di < 64; di++) {
            float q0 = myqs[di];
            float q1 = myqs[64 + di];
            float q2v = myqs[128 + di];
            float q3 = myqs[192 + di];
            #pragma unroll
            for (int tt = 0; tt < 7; tt++) {
                float kvv = Ks[(lane + 32 * tt) * 65 + di];
                acc[0][tt] += q0  * kvv;
                acc[1][tt] += q1  * kvv;
                acc[2][tt] += q2v * kvv;
                acc[3][tt] += q3  * kvv;
            }
        }

        float rinv[4];
        #pragma unroll
        for (int u = 0; u < 4; u++) {
            float m = -1e30f;
            #pragma unroll
            for (int tt = 0; tt < 7; tt++) {
                int j = lane + 32 * tt;
                if (j < P_) m = fmaxf(m, acc[u][tt] * SCALE);
            }
            #pragma unroll
            for (int off = 16; off; off >>= 1)
                m = fmaxf(m, __shfl_xor_sync(0xffffffffu, m, off));
            float lsum = 0.f;
            #pragma unroll
            for (int tt = 0; tt < 7; tt++) {
                int j = lane + 32 * tt;
                if (j < P_) {
                    float p = __expf(acc[u][tt] * SCALE - m);
                    myps[u * 196 + j] = p;
                    lsum += p;
                }
            }
            #pragma unroll
            for (int off = 16; off; off >>= 1)
                lsum += __shfl_xor_sync(0xffffffffu, lsum, off);
            rinv[u] = 1.f / lsum;
        }
        __syncwarp();

        float o[4][2];
        #pragma unroll
        for (int u = 0; u < 4; u++) { o[u][0] = 0.f; o[u][1] = 0.f; }
        #pragma unroll 2
        for (int j = 0; j < P_; j++) {
            float v0 = Vs[j * 65 + lane];
            float v1 = Vs[j * 65 + lane + 32];
            #pragma unroll
            for (int u = 0; u < 4; u++) {
                float p = myps[u * 196 + j];
                o[u][0] += p * v0;
                o[u][1] += p * v1;
            }
        }
        #pragma unroll
        for (int u = 0; u < 4; u++) {
            float* op = g_traj + ((size_t)(b * S_ + sq0 + u) * F_ + f) * C_ + head * D_;
            op[lane]      = o[u][0] * rinv[u];
            op[lane + 32] = o[u][1] * rinv[u];
        }
        __syncwarp();
    }
}

// ======================================================================
// x_diag gather
// ======================================================================
__global__ __launch_bounds__(256) void xdiag_kernel()
{
    int i = blockIdx.x * 256 + threadIdx.x;
    if (i >= B_ * S_ * C_) return;
    int c = i % C_;
    int r = i / C_;
    int s = r % S_;
    g_xdiag[i] = g_traj[((size_t)r * F_ + (s / P_)) * C_ + c];
}

// ======================================================================
// Final frame attention (unchanged)
// ======================================================================
__global__ __launch_bounds__(256) void final_attn_kernel(float* __restrict__ attn_out)
{
    int gw   = (blockIdx.x * 256 + threadIdx.x) >> 5;
    int lane = threadIdx.x & 31;
    if (gw >= B_ * H_ * S_) return;
    int b    = gw / (H_ * S_);
    int r    = gw % (H_ * S_);
    int head = r / S_;
    int s    = r % S_;

    const float* q2p = g_q2 + ((size_t)b * S_ + s) * C_ + head * D_;
    float q0 = q2p[lane];
    float q1 = q2p[lane + 32];

    const float* k2p = g_k2 + ((size_t)b * S_ + s) * (size_t)F_ * C_ + head * D_;
    float lg[8];
    #pragma unroll
    for (int f = 0; f < 8; f++) {
        float t = q0 * k2p[f * C_ + lane] + q1 * k2p[f * C_ + lane + 32];
        #pragma unroll
        for (int off = 16; off; off >>= 1)
            t += __shfl_xor_sync(0xffffffffu, t, off);
        lg[f] = t;
    }
    float m = lg[0];
    #pragma unroll
    for (int f = 1; f < 8; f++) m = fmaxf(m, lg[f]);
    float p[8], sum = 0.f;
    #pragma unroll
    for (int f = 0; f < 8; f++) { p[f] = __expf(lg[f] - m); sum += p[f]; }
    float inv = 1.f / sum;

    float* ap = attn_out + (((size_t)b * H_ + head) * S_ + s) * F_;
    #pragma unroll
    for (int f = 0; f < 8; f++)
        if (lane == f) ap[f] = p[f] * inv;

    const float* tp = g_traj + ((size_t)b * S_ + s) * (size_t)F_ * C_ + head * D_;
    float o0 = 0.f, o1 = 0.f;
    #pragma unroll
    for (int f = 0; f < 8; f++) {
        float pf = p[f] * inv;
        o0 += pf * tp[f * C_ + lane];
        o1 += pf * tp[f * C_ + lane + 32];
    }
    float* op = g_attin + ((size_t)b * N_ + 1 + s) * C_ + head * D_;
    op[lane]      = o0;
    op[lane + 32] = o1;
}

// ======================================================================
// Host launcher
// ======================================================================
extern "C" void kernel_launch(void* const* d_in, const int* in_sizes, int n_in,
                              void* d_out, int out_size)
{
    const float* x      = (const float*)d_in[0];
    const float* W_qkv  = (const float*)d_in[1];
    const float* W_pq   = (const float*)d_in[2];
    const float* W_pkv  = (const float*)d_in[3];
    const float* W_proj = (const float*)d_in[4];
    const float* b_proj = (const float*)d_in[5];

    float* out  = (float*)d_out;
    float* attn = out + (size_t)B_ * N_ * C_;

    float *qkv, *traj, *xdiag, *q2, *k2, *attin;
    cudaGetSymbolAddress((void**)&qkv,   g_qkv);
    cudaGetSymbolAddress((void**)&traj,  g_traj);
    cudaGetSymbolAddress((void**)&xdiag, g_xdiag);
    cudaGetSymbolAddress((void**)&q2,    g_q2);
    cudaGetSymbolAddress((void**)&k2,    g_k2);
    cudaGetSymbolAddress((void**)&attin, g_attin);

    // 1) qkv = x @ W_qkv      (3138 x 2304 x 768)
    gemm_tf32_k<<<dim3(C3_ / 128, (B_ * N_ + 127) / 128), 256>>>(
        x, C_, W_qkv, C3_, qkv, C3_, B_ * N_, C_, 1.f, nullptr);

    // 2) cls attention -> g_attin rows 0
    cls_attn_kernel<<<B_ * H_, 256>>>();

    // 3) space attention -> g_traj (B,S,F,C)
    cudaFuncSetAttribute(space_attn_kernel,
                         cudaFuncAttributeMaxDynamicSharedMemorySize, SA_SMEM_BYTES);
    space_attn_kernel<<<dim3(8, F_, B_ * H_), SA_THREADS, SA_SMEM_BYTES>>>();

    // 4) x_diag gather
    xdiag_kernel<<<(B_ * S_ * C_) / 256, 256>>>();

    // 5) q2 = scale * (x_diag @ W_pq)    (3136 x 768 x 768)
    gemm_tf32_k<<<dim3(C_ / 128, (B_ * S_ + 127) / 128), 256>>>(
        xdiag, C_, W_pq, C_, q2, C_, B_ * S_, C_, SCALE, nullptr);

    // 6) k2 = traj @ W_pkv[:, :C]        (25088 x 768 x 768)   [v2 is dead code]
    gemm_tf32_k<<<dim3(C_ / 128, (B_ * S_ * F_) / 128), 256>>>(
        traj, C_, W_pkv, 2 * C_, k2, C_, B_ * S_ * F_, C_, 1.f, nullptr);

    // 7) frame softmax + weighted traj sum -> attn output + g_attin rows 1..
    final_attn_kernel<<<(B_ * H_ * S_ * 32) / 256, 256>>>(attn);

    // 8) out = concat(cls, out_pre) @ W_proj + b_proj -> d_out
    gemm_tf32_k<<<dim3(C_ / 128, (B_ * N_ + 127) / 128), 256>>>(
        attin, C_, W_proj, C_, out, C_, B_ * N_, C_, 1.f, b_proj);
}

// round 8
// speedup vs baseline: 2.7991x; 1.6075x over previous
#include <cuda_runtime.h>
#include <cstdint>
#include <cstddef>

// ---------------- problem constants ----------------
#define B_   2
#define N_   1569
#define C_   768
#define H_   12
#define D_   64
#define P_   196
#define F_   8
#define S_   1568          // F_*P_ = N_-1
#define C3_  2304          // 3*C_
#define SCALE 0.125f       // d^-0.5 = 1/8

// ---------------- scratch (device globals) ----------------
__device__ float g_qkv  [B_*N_*C3_];
__device__ float g_traj [B_*S_*F_*C_];
__device__ float g_q2   [B_*S_*C_];
__device__ float g_k2   [B_*S_*F_*C_];
__device__ float g_attin[B_*N_*C_];

// ---------------- helpers ----------------
__device__ __forceinline__ uint32_t f2tf32(float f) {
    uint32_t o;
    asm("cvt.rna.tf32.f32 %0, %1;" : "=r"(o) : "f"(f));
    return o;
}
__device__ __forceinline__ void cp16(void* dst, const void* src, bool p) {
    uint32_t d = (uint32_t)__cvta_generic_to_shared(dst);
    int sz = p ? 16 : 0;
    asm volatile("cp.async.ca.shared.global [%0], [%1], 16, %2;"
                 :: "r"(d), "l"(src), "r"(sz));
}
__device__ __forceinline__ void cp_commit() {
    asm volatile("cp.async.commit_group;");
}
__device__ __forceinline__ void mma_tf32(float* c,
    uint32_t a0, uint32_t a1, uint32_t a2, uint32_t a3,
    uint32_t b0, uint32_t b1)
{
    asm volatile(
        "mma.sync.aligned.m16n8k8.row.col.f32.tf32.tf32.f32 "
        "{%0,%1,%2,%3}, {%4,%5,%6,%7}, {%8,%9}, {%0,%1,%2,%3};"
        : "+f"(c[0]), "+f"(c[1]), "+f"(c[2]), "+f"(c[3])
        : "r"(a0), "r"(a1), "r"(a2), "r"(a3), "r"(b0), "r"(b1));
}

// ======================================================================
// TF32 GEMM with cp.async double buffering.
// C[M,N] = alpha * A[M,K] @ B[K,N] (+ bias). BM=BN=128, BK=32, 256 thr.
// diagmode=1: A row r maps to traj row (r*F + (r%S)/P)  [xdiag fusion].
// Dynamic smem: As 2x128x36 f32, Bs 2x32x136 f32 = 71680 B.
// ======================================================================
#define GEMM_SMEM_BYTES ((2*128*36 + 2*32*136) * 4)

__global__ __launch_bounds__(256) void gemm_tf32_db(
    const float* __restrict__ A, int lda,
    const float* __restrict__ Bw, int ldb,
    float* __restrict__ Cc, int ldc,
    int M, int K, float alpha, const float* __restrict__ bias, int diagmode)
{
    extern __shared__ float gsm[];
    float* As = gsm;                 // [2][128*36]
    float* Bs = gsm + 2 * 128 * 36;  // [2][32*136]

    const int tid    = threadIdx.x;
    const int warp   = tid >> 5;
    const int lane   = tid & 31;
    const int g      = lane >> 2;
    const int t      = lane & 3;
    const int warp_m = warp >> 2;
    const int warp_n = warp & 3;
    const int row0   = blockIdx.y * 128;
    const int col0   = blockIdx.x * 128;

    float acc[4][4][4];
    #pragma unroll
    for (int mt = 0; mt < 4; mt++)
        #pragma unroll
        for (int nt = 0; nt < 4; nt++)
            #pragma unroll
            for (int r = 0; r < 4; r++) acc[mt][nt][r] = 0.f;

    const int ntiles = K / 32;

    auto issue_tile = [&](int buf, int k0) {
        float* Ab = As + buf * 128 * 36;
        float* Bb = Bs + buf * 32 * 136;
        #pragma unroll
        for (int i = 0; i < 4; i++) {
            int idx = tid + i * 256;
            int r   = idx >> 3;
            int c   = (idx & 7) * 4;
            int gr  = row0 + r;
            const float* src;
            if (diagmode) {
                int s = gr % S_;
                src = A + ((size_t)gr * F_ + (s / P_)) * C_ + k0 + c;
            } else {
                src = A + (size_t)gr * lda + k0 + c;
            }
            cp16(Ab + r * 36 + c, src, gr < M);
        }
        #pragma unroll
        for (int i = 0; i < 4; i++) {
            int idx = tid + i * 256;
            int r   = idx >> 5;
            int c   = (idx & 31) * 4;
            cp16(Bb + r * 136 + c, Bw + (size_t)(k0 + r) * ldb + col0 + c, true);
        }
        cp_commit();
    };

    issue_tile(0, 0);

    for (int kt = 0; kt < ntiles; kt++) {
        int cur = kt & 1;
        if (kt + 1 < ntiles) {
            issue_tile(cur ^ 1, (kt + 1) * 32);
            asm volatile("cp.async.wait_group 1;");
        } else {
            asm volatile("cp.async.wait_group 0;");
        }
        __syncthreads();

        const float* Ab = As + cur * 128 * 36;
        const float* Bb = Bs + cur * 32 * 136;

        #pragma unroll
        for (int kk = 0; kk < 32; kk += 8) {
            uint32_t a[4][4], bf[4][2];
            #pragma unroll
            for (int mt = 0; mt < 4; mt++) {
                int r = warp_m * 64 + mt * 16 + g;
                const float* p = &Ab[r * 36 + kk + t];
                a[mt][0] = f2tf32(p[0]);
                a[mt][1] = f2tf32(p[8 * 36]);
                a[mt][2] = f2tf32(p[4]);
                a[mt][3] = f2tf32(p[8 * 36 + 4]);
            }
            #pragma unroll
            for (int nt = 0; nt < 4; nt++) {
                int c = warp_n * 32 + nt * 8 + g;
                const float* p = &Bb[(kk + t) * 136 + c];
                bf[nt][0] = f2tf32(p[0]);
                bf[nt][1] = f2tf32(p[4 * 136]);
            }
            #pragma unroll
            for (int mt = 0; mt < 4; mt++)
                #pragma unroll
                for (int nt = 0; nt < 4; nt++)
                    mma_tf32(acc[mt][nt], a[mt][0], a[mt][1], a[mt][2], a[mt][3],
                             bf[nt][0], bf[nt][1]);
        }
        __syncthreads();
    }

    #pragma unroll
    for (int nt = 0; nt < 4; nt++) {
        int c = col0 + warp_n * 32 + nt * 8 + t * 2;
        float b0 = bias ? bias[c]     : 0.f;
        float b1 = bias ? bias[c + 1] : 0.f;
        #pragma unroll
        for (int mt = 0; mt < 4; mt++) {
            int r = row0 + warp_m * 64 + mt * 16 + g;
            if (r < M) {
                float* cp = Cc + (size_t)r * ldc + c;
                cp[0] = acc[mt][nt][0] * alpha + b0;
                cp[1] = acc[mt][nt][1] * alpha + b1;
            }
            if (r + 8 < M) {
                float* cp = Cc + (size_t)(r + 8) * ldc + c;
                cp[0] = acc[mt][nt][2] * alpha + b0;
                cp[1] = acc[mt][nt][3] * alpha + b1;
            }
        }
    }
}

// ======================================================================
// Space attention on tensor cores.
// Block = (q-tile of 128, frame f, bh); 256 threads = 8 warps, 16 q/warp.
// Keys padded 196 -> 200 (25 n-tiles). Scores in registers, softmax via
// 4-lane shuffles, C-frag -> A-frag shuffle for P@V.
// Smem (tf32 words): Qs 128x68, Ks 200x68, Vs 200x72  = 146816 B.
// ======================================================================
#define SAT_SMEM_BYTES ((128*68 + 200*68 + 200*72) * 4)

__global__ __launch_bounds__(256) void space_attn_mma()
{
    extern __shared__ uint32_t ssm[];
    uint32_t* Qs = ssm;                  // [128][68]
    uint32_t* Ks = ssm + 128 * 68;       // [200][68]
    uint32_t* Vs = Ks + 200 * 68;        // [200][72]

    const int qt   = blockIdx.x;      // 0..12
    const int f    = blockIdx.y;
    const int bh   = blockIdx.z;
    const int b    = bh / H_;
    const int head = bh % H_;
    const int tid  = threadIdx.x;
    const int w    = tid >> 5;
    const int lane = tid & 31;
    const int g    = lane >> 2;
    const int t    = lane & 3;

    const float* base = g_qkv + (size_t)b * N_ * C3_;

    // ---- load Q tile (128 x 64), tf32 ----
    #pragma unroll
    for (int i = 0; i < 8; i++) {
        int idx = tid + i * 256;
        int r   = idx >> 4;
        int cf  = (idx & 15) * 4;
        int sq  = qt * 128 + r;
        float4 v = make_float4(0.f, 0.f, 0.f, 0.f);
        if (sq < S_)
            v = *(const float4*)(base + (size_t)(1 + sq) * C3_ + head * D_ + cf);
        uint32_t* d = &Qs[r * 68 + cf];
        d[0] = f2tf32(v.x); d[1] = f2tf32(v.y);
        d[2] = f2tf32(v.z); d[3] = f2tf32(v.w);
    }
    // ---- load K,V tiles (200 x 64, rows >=196 zero) ----
    for (int idx = tid; idx < 3200; idx += 256) {
        int r  = idx >> 4;
        int cf = (idx & 15) * 4;
        float4 kv = make_float4(0.f, 0.f, 0.f, 0.f);
        float4 vv = make_float4(0.f, 0.f, 0.f, 0.f);
        if (r < P_) {
            const float* row = base + (size_t)(1 + f * P_ + r) * C3_ + head * D_ + cf;
            kv = *(const float4*)(row + C_);
            vv = *(const float4*)(row + 2 * C_);
        }
        uint32_t* dk = &Ks[r * 68 + cf];
        dk[0] = f2tf32(kv.x); dk[1] = f2tf32(kv.y);
        dk[2] = f2tf32(kv.z); dk[3] = f2tf32(kv.w);
        uint32_t* dv = &Vs[r * 72 + cf];
        dv[0] = f2tf32(vv.x); dv[1] = f2tf32(vv.y);
        dv[2] = f2tf32(vv.z); dv[3] = f2tf32(vv.w);
    }
    __syncthreads();

    const int q0 = w * 16;
    if (qt * 128 + q0 >= S_) return;      // inactive warps in last tile

    // ---- Q fragments (reused across all key n-tiles) ----
    uint32_t qa[8][4];
    #pragma unroll
    for (int kk = 0; kk < 8; kk++) {
        qa[kk][0] = Qs[(q0 + g) * 68 + 8 * kk + t];
        qa[kk][1] = Qs[(q0 + 8 + g) * 68 + 8 * kk + t];
        qa[kk][2] = Qs[(q0 + g) * 68 + 8 * kk + t + 4];
        qa[kk][3] = Qs[(q0 + 8 + g) * 68 + 8 * kk + t + 4];
    }

    // ---- scores: S = Q @ K^T  (16 x 200 per warp) ----
    float s[25][4];
    #pragma unroll
    for (int nt = 0; nt < 25; nt++) {
        s[nt][0] = s[nt][1] = s[nt][2] = s[nt][3] = 0.f;
        #pragma unroll
        for (int kk = 0; kk < 8; kk++) {
            uint32_t b0 = Ks[(8 * nt + g) * 68 + 8 * kk + t];
            uint32_t b1 = Ks[(8 * nt + g) * 68 + 8 * kk + t + 4];
            mma_tf32(s[nt], qa[kk][0], qa[kk][1], qa[kk][2], qa[kk][3], b0, b1);
        }
    }
    // scale + mask padded keys (cols 196..199 live in nt=24, t>=2)
    #pragma unroll
    for (int nt = 0; nt < 25; nt++) {
        s[nt][0] *= SCALE; s[nt][1] *= SCALE;
        s[nt][2] *= SCALE; s[nt][3] *= SCALE;
    }
    if (t >= 2) { s[24][0] = s[24][1] = s[24][2] = s[24][3] = -1e30f; }

    // ---- softmax over 200 cols (rows g and g+8) ----
    float mlo = -1e30f, mhi = -1e30f;
    #pragma unroll
    for (int nt = 0; nt < 25; nt++) {
        mlo = fmaxf(mlo, fmaxf(s[nt][0], s[nt][1]));
        mhi = fmaxf(mhi, fmaxf(s[nt][2], s[nt][3]));
    }
    mlo = fmaxf(mlo, __shfl_xor_sync(0xffffffffu, mlo, 1));
    mlo = fmaxf(mlo, __shfl_xor_sync(0xffffffffu, mlo, 2));
    mhi = fmaxf(mhi, __shfl_xor_sync(0xffffffffu, mhi, 1));
    mhi = fmaxf(mhi, __shfl_xor_sync(0xffffffffu, mhi, 2));

    float slo = 0.f, shi = 0.f;
    #pragma unroll
    for (int nt = 0; nt < 25; nt++) {
        s[nt][0] = __expf(s[nt][0] - mlo); slo += s[nt][0];
        s[nt][1] = __expf(s[nt][1] - mlo); slo += s[nt][1];
        s[nt][2] = __expf(s[nt][2] - mhi); shi += s[nt][2];
        s[nt][3] = __expf(s[nt][3] - mhi); shi += s[nt][3];
    }
    slo += __shfl_xor_sync(0xffffffffu, slo, 1);
    slo += __shfl_xor_sync(0xffffffffu, slo, 2);
    shi += __shfl_xor_sync(0xffffffffu, shi, 1);
    shi += __shfl_xor_sync(0xffffffffu, shi, 2);
    float rlo = 1.f / slo, rhi = 1.f / shi;
    #pragma unroll
    for (int nt = 0; nt < 25; nt++) {
        s[nt][0] *= rlo; s[nt][1] *= rlo;
        s[nt][2] *= rhi; s[nt][3] *= rhi;
    }

    // ---- out = P @ V  (16 x 64 per warp) ----
    float o[8][4];
    #pragma unroll
    for (int n = 0; n < 8; n++)
        o[n][0] = o[n][1] = o[n][2] = o[n][3] = 0.f;

    const int src0 = (lane & ~3) | (t >> 1);
    const int src1 = src0 | 2;

    #pragma unroll
    for (int kk = 0; kk < 25; kk++) {
        float x0 = __shfl_sync(0xffffffffu, s[kk][0], src0);
        float x1 = __shfl_sync(0xffffffffu, s[kk][1], src0);
        float x2 = __shfl_sync(0xffffffffu, s[kk][2], src0);
        float x3 = __shfl_sync(0xffffffffu, s[kk][3], src0);
        float y0 = __shfl_sync(0xffffffffu, s[kk][0], src1);
        float y1 = __shfl_sync(0xffffffffu, s[kk][1], src1);
        float y2 = __shfl_sync(0xffffffffu, s[kk][2], src1);
        float y3 = __shfl_sync(0xffffffffu, s[kk][3], src1);
        uint32_t pa0 = f2tf32((t & 1) ? x1 : x0);   // P[g][8kk+t]
        uint32_t pa1 = f2tf32((t & 1) ? x3 : x2);   // P[g+8][8kk+t]
        uint32_t pa2 = f2tf32((t & 1) ? y1 : y0);   // P[g][8kk+t+4]
        uint32_t pa3 = f2tf32((t & 1) ? y3 : y2);   // P[g+8][8kk+t+4]
        #pragma unroll
        for (int n = 0; n < 8; n++) {
            uint32_t b0 = Vs[(8 * kk + t) * 72 + 8 * n + g];
            uint32_t b1 = Vs[(8 * kk + t + 4) * 72 + 8 * n + g];
            mma_tf32(o[n], pa0, pa1, pa2, pa3, b0, b1);
        }
    }

    // ---- store to g_traj (B,S,F,C), head-concat ----
    const int r1 = qt * 128 + q0 + g;
    const int r2 = r1 + 8;
    #pragma unroll
    for (int n = 0; n < 8; n++) {
        int c = head * D_ + 8 * n + 2 * t;
        float* p1 = g_traj + ((size_t)(b * S_ + r1) * F_ + f) * C_ + c;
        p1[0] = o[n][0]; p1[1] = o[n][1];
        float* p2 = g_traj + ((size_t)(b * S_ + r2) * F_ + f) * C_ + c;
        p2[0] = o[n][2]; p2[1] = o[n][3];
    }
}

// ======================================================================
// CLS attention (unchanged)
// ======================================================================
__global__ __launch_bounds__(256) void cls_attn_kernel()
{
    __shared__ float sims[N_];
    __shared__ float q0s[64];
    __shared__ float red[9];

    const int bh   = blockIdx.x;
    const int b    = bh / H_;
    const int head = bh % H_;
    const int tid  = threadIdx.x;
    const int w    = tid >> 5;
    const int lane = tid & 31;

    const float* base = g_qkv + (size_t)b * N_ * C3_;

    if (tid < 64) q0s[tid] = base[head * D_ + tid];
    __syncthreads();

    for (int j = tid; j < N_; j += 256) {
        const float* kr = base + (size_t)j * C3_ + C_ + head * D_;
        float dsum = 0.f;
        #pragma unroll
        for (int di = 0; di < 64; di += 4) {
            float4 kv = *(const float4*)(kr + di);
            dsum += q0s[di] * kv.x + q0s[di + 1] * kv.y
                  + q0s[di + 2] * kv.z + q0s[di + 3] * kv.w;
        }
        sims[j] = dsum * SCALE;
    }
    __syncthreads();

    float m = -1e30f;
    for (int j = tid; j < N_; j += 256) m = fmaxf(m, sims[j]);
    #pragma unroll
    for (int off = 16; off; off >>= 1) m = fmaxf(m, __shfl_xor_sync(0xffffffffu, m, off));
    if (lane == 0) red[w] = m;
    __syncthreads();
    if (tid == 0) {
        float mm = red[0];
        #pragma unroll
        for (int i = 1; i < 8; i++) mm = fmaxf(mm, red[i]);
        red[8] = mm;
    }
    __syncthreads();
    const float M = red[8];
    __syncthreads();

    float ls = 0.f;
    for (int j = tid; j < N_; j += 256) {
        float p = __expf(sims[j] - M);
        sims[j] = p;
        ls += p;
    }
    #pragma unroll
    for (int off = 16; off; off >>= 1) ls += __shfl_xor_sync(0xffffffffu, ls, off);
    if (lane == 0) red[w] = ls;
    __syncthreads();
    if (tid == 0) {
        float ss = 0.f;
        #pragma unroll
        for (int i = 0; i < 8; i++) ss += red[i];
        red[8] = ss;
    }
    __syncthreads();
    const float SUM = red[8];

    if (tid < 64) {
        float acc = 0.f;
        const float* vcol = base + 2 * C_ + head * D_ + tid;
        #pragma unroll 4
        for (int j = 0; j < N_; j++)
            acc += sims[j] * vcol[(size_t)j * C3_];
        g_attin[(size_t)b * N_ * C_ + head * D_ + tid] = acc / SUM;
    }
}

// ======================================================================
// Final frame attention (unchanged)
// ======================================================================
__global__ __launch_bounds__(256) void final_attn_kernel(float* __restrict__ attn_out)
{
    int gw   = (blockIdx.x * 256 + threadIdx.x) >> 5;
    int lane = threadIdx.x & 31;
    if (gw >= B_ * H_ * S_) return;
    int b    = gw / (H_ * S_);
    int r    = gw % (H_ * S_);
    int head = r / S_;
    int s    = r % S_;

    const float* q2p = g_q2 + ((size_t)b * S_ + s) * C_ + head * D_;
    float q0 = q2p[lane];
    float q1 = q2p[lane + 32];

    const float* k2p = g_k2 + ((size_t)b * S_ + s) * (size_t)F_ * C_ + head * D_;
    float lg[8];
    #pragma unroll
    for (int f = 0; f < 8; f++) {
        float tt = q0 * k2p[f * C_ + lane] + q1 * k2p[f * C_ + lane + 32];
        #pragma unroll
        for (int off = 16; off; off >>= 1)
            tt += __shfl_xor_sync(0xffffffffu, tt, off);
        lg[f] = tt;
    }
    float m = lg[0];
    #pragma unroll
    for (int f = 1; f < 8; f++) m = fmaxf(m, lg[f]);
    float p[8], sum = 0.f;
    #pragma unroll
    for (int f = 0; f < 8; f++) { p[f] = __expf(lg[f] - m); sum += p[f]; }
    float inv = 1.f / sum;

    float* ap = attn_out + (((size_t)b * H_ + head) * S_ + s) * F_;
    #pragma unroll
    for (int f = 0; f < 8; f++)
        if (lane == f) ap[f] = p[f] * inv;

    const float* tp = g_traj + ((size_t)b * S_ + s) * (size_t)F_ * C_ + head * D_;
    float o0 = 0.f, o1 = 0.f;
    #pragma unroll
    for (int f = 0; f < 8; f++) {
        float pf = p[f] * inv;
        o0 += pf * tp[f * C_ + lane];
        o1 += pf * tp[f * C_ + lane + 32];
    }
    float* op = g_attin + ((size_t)b * N_ + 1 + s) * C_ + head * D_;
    op[lane]      = o0;
    op[lane + 32] = o1;
}

// ======================================================================
// Host launcher
// ======================================================================
extern "C" void kernel_launch(void* const* d_in, const int* in_sizes, int n_in,
                              void* d_out, int out_size)
{
    const float* x      = (const float*)d_in[0];
    const float* W_qkv  = (const float*)d_in[1];
    const float* W_pq   = (const float*)d_in[2];
    const float* W_pkv  = (const float*)d_in[3];
    const float* W_proj = (const float*)d_in[4];
    const float* b_proj = (const float*)d_in[5];

    float* out  = (float*)d_out;
    float* attn = out + (size_t)B_ * N_ * C_;

    float *qkv, *traj, *q2, *k2, *attin;
    cudaGetSymbolAddress((void**)&qkv,   g_qkv);
    cudaGetSymbolAddress((void**)&traj,  g_traj);
    cudaGetSymbolAddress((void**)&q2,    g_q2);
    cudaGetSymbolAddress((void**)&k2,    g_k2);
    cudaGetSymbolAddress((void**)&attin, g_attin);

    cudaFuncSetAttribute(gemm_tf32_db,
                         cudaFuncAttributeMaxDynamicSharedMemorySize, GEMM_SMEM_BYTES);
    cudaFuncSetAttribute(space_attn_mma,
                         cudaFuncAttributeMaxDynamicSharedMemorySize, SAT_SMEM_BYTES);

    // 1) qkv = x @ W_qkv      (3138 x 2304 x 768)
    gemm_tf32_db<<<dim3(C3_ / 128, (B_ * N_ + 127) / 128), 256, GEMM_SMEM_BYTES>>>(
        x, C_, W_qkv, C3_, qkv, C3_, B_ * N_, C_, 1.f, nullptr, 0);

    // 2) cls attention -> g_attin rows 0
    cls_attn_kernel<<<B_ * H_, 256>>>();

    // 3) space attention -> g_traj (tensor cores)
    space_attn_mma<<<dim3(13, F_, B_ * H_), 256, SAT_SMEM_BYTES>>>();

    // 4) q2 = scale * (x_diag @ W_pq)  (diag gather fused into A-load)
    gemm_tf32_db<<<dim3(C_ / 128, (B_ * S_ + 127) / 128), 256, GEMM_SMEM_BYTES>>>(
        traj, 0, W_pq, C_, q2, C_, B_ * S_, C_, SCALE, nullptr, 1);

    // 5) k2 = traj @ W_pkv[:, :C]      (25088 x 768 x 768)  [v2 dead code]
    gemm_tf32_db<<<dim3(C_ / 128, (B_ * S_ * F_) / 128), 256, GEMM_SMEM_BYTES>>>(
        traj, C_, W_pkv, 2 * C_, k2, C_, B_ * S_ * F_, C_, 1.f, nullptr, 0);

    // 6) frame softmax + weighted traj sum -> attn + g_attin rows 1..
    final_attn_kernel<<<(B_ * H_ * S_ * 32) / 256, 256>>>(attn);

    // 7) out = concat(cls, out_pre) @ W_proj + b_proj -> d_out
    gemm_tf32_db<<<dim3(C_ / 128, (B_ * N_ + 127) / 128), 256, GEMM_SMEM_BYTES>>>(
        attin, C_, W_proj, C_, out, C_, B_ * N_, C_, 1.f, b_proj, 0);
}

// round 9
// speedup vs baseline: 2.8823x; 1.0297x over previous
#include <cuda_runtime.h>
#include <cstdint>
#include <cstddef>

// ---------------- problem constants ----------------
#define B_   2
#define N_   1569
#define C_   768
#define H_   12
#define D_   64
#define P_   196
#define F_   8
#define S_   1568          // F_*P_ = N_-1
#define C3_  2304          // 3*C_
#define SCALE 0.125f       // d^-0.5 = 1/8

// ---------------- scratch (device globals) ----------------
__device__ float g_qkv  [B_*N_*C3_];
__device__ float g_traj [B_*S_*F_*C_];   // stored tf32-rounded
__device__ float g_q2   [B_*S_*C_];
__device__ float g_k2   [B_*S_*F_*C_];
__device__ float g_attin[B_*N_*C_];      // stored tf32-rounded
// tf32-rounded copies of external GEMM operands
__device__ float g_xr    [B_*N_*C_];
__device__ float g_wqkvr [C_*C3_];
__device__ float g_wpqr  [C_*C_];
__device__ float g_wpkvr [C_*2*C_];
__device__ float g_wprojr[C_*C_];

// ---------------- helpers ----------------
__device__ __forceinline__ uint32_t f2tf32(float f) {
    uint32_t o;
    asm("cvt.rna.tf32.f32 %0, %1;" : "=r"(o) : "f"(f));
    return o;
}
__device__ __forceinline__ float roundtf32(float f) {
    return __uint_as_float(f2tf32(f));
}
__device__ __forceinline__ void cp16(void* dst, const void* src, bool p) {
    uint32_t d = (uint32_t)__cvta_generic_to_shared(dst);
    int sz = p ? 16 : 0;
    asm volatile("cp.async.ca.shared.global [%0], [%1], 16, %2;"
                 :: "r"(d), "l"(src), "r"(sz));
}
__device__ __forceinline__ void cp_commit() {
    asm volatile("cp.async.commit_group;");
}
__device__ __forceinline__ void mma_tf32(float* c,
    uint32_t a0, uint32_t a1, uint32_t a2, uint32_t a3,
    uint32_t b0, uint32_t b1)
{
    asm volatile(
        "mma.sync.aligned.m16n8k8.row.col.f32.tf32.tf32.f32 "
        "{%0,%1,%2,%3}, {%4,%5,%6,%7}, {%8,%9}, {%0,%1,%2,%3};"
        : "+f"(c[0]), "+f"(c[1]), "+f"(c[2]), "+f"(c[3])
        : "r"(a0), "r"(a1), "r"(a2), "r"(a3), "r"(b0), "r"(b1));
}

// ======================================================================
// Pre-pass: round a tensor to tf32 (rna) into scratch. n % 4 == 0.
// ======================================================================
__global__ __launch_bounds__(256) void round_tf32_kernel(
    const float* __restrict__ src, float* __restrict__ dst, int n)
{
    int i = (blockIdx.x * 256 + threadIdx.x) * 4;
    if (i >= n) return;
    float4 v = *(const float4*)(src + i);
    v.x = roundtf32(v.x); v.y = roundtf32(v.y);
    v.z = roundtf32(v.z); v.w = roundtf32(v.w);
    *(float4*)(dst + i) = v;
}

// ======================================================================
// TF32 GEMM, cp.async double buffered, cvt-free mainloop (operands are
// pre-rounded to tf32; raw bits fed to MMA are exact).
// C[M,N] = alpha * A[M,K] @ B[K,N] (+ bias). BM=BN=128, BK=32, 256 thr.
// diagmode=1: A row r maps to traj row (r*F + (r%S)/P)  [xdiag fusion].
// Dynamic smem: As 2x128x36 f32, Bs 2x32x136 f32 = 71680 B.
// ======================================================================
#define GEMM_SMEM_BYTES ((2*128*36 + 2*32*136) * 4)

__global__ __launch_bounds__(256, 2) void gemm_tf32_db(
    const float* __restrict__ A, int lda,
    const float* __restrict__ Bw, int ldb,
    float* __restrict__ Cc, int ldc,
    int M, int K, float alpha, const float* __restrict__ bias, int diagmode)
{
    extern __shared__ float gsm[];
    float* As = gsm;                 // [2][128*36]
    float* Bs = gsm + 2 * 128 * 36;  // [2][32*136]

    const int tid    = threadIdx.x;
    const int warp   = tid >> 5;
    const int lane   = tid & 31;
    const int g      = lane >> 2;
    const int t      = lane & 3;
    const int warp_m = warp >> 2;
    const int warp_n = warp & 3;
    const int row0   = blockIdx.y * 128;
    const int col0   = blockIdx.x * 128;

    float acc[4][4][4];
    #pragma unroll
    for (int mt = 0; mt < 4; mt++)
        #pragma unroll
        for (int nt = 0; nt < 4; nt++)
            #pragma unroll
            for (int r = 0; r < 4; r++) acc[mt][nt][r] = 0.f;

    const int ntiles = K / 32;

    auto issue_tile = [&](int buf, int k0) {
        float* Ab = As + buf * 128 * 36;
        float* Bb = Bs + buf * 32 * 136;
        #pragma unroll
        for (int i = 0; i < 4; i++) {
            int idx = tid + i * 256;
            int r   = idx >> 3;
            int c   = (idx & 7) * 4;
            int gr  = row0 + r;
            const float* src;
            if (diagmode) {
                int s = gr % S_;
                src = A + ((size_t)gr * F_ + (s / P_)) * C_ + k0 + c;
            } else {
                src = A + (size_t)gr * lda + k0 + c;
            }
            cp16(Ab + r * 36 + c, src, gr < M);
        }
        #pragma unroll
        for (int i = 0; i < 4; i++) {
            int idx = tid + i * 256;
            int r   = idx >> 5;
            int c   = (idx & 31) * 4;
            cp16(Bb + r * 136 + c, Bw + (size_t)(k0 + r) * ldb + col0 + c, true);
        }
        cp_commit();
    };

    issue_tile(0, 0);

    for (int kt = 0; kt < ntiles; kt++) {
        int cur = kt & 1;
        if (kt + 1 < ntiles) {
            issue_tile(cur ^ 1, (kt + 1) * 32);
            asm volatile("cp.async.wait_group 1;");
        } else {
            asm volatile("cp.async.wait_group 0;");
        }
        __syncthreads();

        const uint32_t* Ab = (const uint32_t*)(As + cur * 128 * 36);
        const uint32_t* Bb = (const uint32_t*)(Bs + cur * 32 * 136);

        #pragma unroll
        for (int kk = 0; kk < 32; kk += 8) {
            uint32_t a[4][4], bf[4][2];
            #pragma unroll
            for (int mt = 0; mt < 4; mt++) {
                int r = warp_m * 64 + mt * 16 + g;
                const uint32_t* p = &Ab[r * 36 + kk + t];
                a[mt][0] = p[0];
                a[mt][1] = p[8 * 36];
                a[mt][2] = p[4];
                a[mt][3] = p[8 * 36 + 4];
            }
            #pragma unroll
            for (int nt = 0; nt < 4; nt++) {
                int c = warp_n * 32 + nt * 8 + g;
                const uint32_t* p = &Bb[(kk + t) * 136 + c];
                bf[nt][0] = p[0];
                bf[nt][1] = p[4 * 136];
            }
            #pragma unroll
            for (int mt = 0; mt < 4; mt++)
                #pragma unroll
                for (int nt = 0; nt < 4; nt++)
                    mma_tf32(acc[mt][nt], a[mt][0], a[mt][1], a[mt][2], a[mt][3],
                             bf[nt][0], bf[nt][1]);
        }
        __syncthreads();
    }

    #pragma unroll
    for (int nt = 0; nt < 4; nt++) {
        int c = col0 + warp_n * 32 + nt * 8 + t * 2;
        float b0 = bias ? bias[c]     : 0.f;
        float b1 = bias ? bias[c + 1] : 0.f;
        #pragma unroll
        for (int mt = 0; mt < 4; mt++) {
            int r = row0 + warp_m * 64 + mt * 16 + g;
            if (r < M) {
                float* cp = Cc + (size_t)r * ldc + c;
                cp[0] = acc[mt][nt][0] * alpha + b0;
                cp[1] = acc[mt][nt][1] * alpha + b1;
            }
            if (r + 8 < M) {
                float* cp = Cc + (size_t)(r + 8) * ldc + c;
                cp[0] = acc[mt][nt][2] * alpha + b0;
                cp[1] = acc[mt][nt][3] * alpha + b1;
            }
        }
    }
}

// ======================================================================
// Space attention on tensor cores (as R8) — stores tf32-rounded traj so
// downstream GEMMs can consume raw bits exactly.
// ======================================================================
#define SAT_SMEM_BYTES ((128*68 + 200*68 + 200*72) * 4)

__global__ __launch_bounds__(256) void space_attn_mma()
{
    extern __shared__ uint32_t ssm[];
    uint32_t* Qs = ssm;                  // [128][68]
    uint32_t* Ks = ssm + 128 * 68;       // [200][68]
    uint32_t* Vs = Ks + 200 * 68;        // [200][72]

    const int qt   = blockIdx.x;      // 0..12
    const int f    = blockIdx.y;
    const int bh   = blockIdx.z;
    const int b    = bh / H_;
    const int head = bh % H_;
    const int tid  = threadIdx.x;
    const int w    = tid >> 5;
    const int lane = tid & 31;
    const int g    = lane >> 2;
    const int t    = lane & 3;

    const float* base = g_qkv + (size_t)b * N_ * C3_;

    #pragma unroll
    for (int i = 0; i < 8; i++) {
        int idx = tid + i * 256;
        int r   = idx >> 4;
        int cf  = (idx & 15) * 4;
        int sq  = qt * 128 + r;
        float4 v = make_float4(0.f, 0.f, 0.f, 0.f);
        if (sq < S_)
            v = *(const float4*)(base + (size_t)(1 + sq) * C3_ + head * D_ + cf);
        uint32_t* d = &Qs[r * 68 + cf];
        d[0] = f2tf32(v.x); d[1] = f2tf32(v.y);
        d[2] = f2tf32(v.z); d[3] = f2tf32(v.w);
    }
    for (int idx = tid; idx < 3200; idx += 256) {
        int r  = idx >> 4;
        int cf = (idx & 15) * 4;
        float4 kv = make_float4(0.f, 0.f, 0.f, 0.f);
        float4 vv = make_float4(0.f, 0.f, 0.f, 0.f);
        if (r < P_) {
            const float* row = base + (size_t)(1 + f * P_ + r) * C3_ + head * D_ + cf;
            kv = *(const float4*)(row + C_);
            vv = *(const float4*)(row + 2 * C_);
        }
        uint32_t* dk = &Ks[r * 68 + cf];
        dk[0] = f2tf32(kv.x); dk[1] = f2tf32(kv.y);
        dk[2] = f2tf32(kv.z); dk[3] = f2tf32(kv.w);
        uint32_t* dv = &Vs[r * 72 + cf];
        dv[0] = f2tf32(vv.x); dv[1] = f2tf32(vv.y);
        dv[2] = f2tf32(vv.z); dv[3] = f2tf32(vv.w);
    }
    __syncthreads();

    const int q0 = w * 16;
    if (qt * 128 + q0 >= S_) return;

    uint32_t qa[8][4];
    #pragma unroll
    for (int kk = 0; kk < 8; kk++) {
        qa[kk][0] = Qs[(q0 + g) * 68 + 8 * kk + t];
        qa[kk][1] = Qs[(q0 + 8 + g) * 68 + 8 * kk + t];
        qa[kk][2] = Qs[(q0 + g) * 68 + 8 * kk + t + 4];
        qa[kk][3] = Qs[(q0 + 8 + g) * 68 + 8 * kk + t + 4];
    }

    float s[25][4];
    #pragma unroll
    for (int nt = 0; nt < 25; nt++) {
        s[nt][0] = s[nt][1] = s[nt][2] = s[nt][3] = 0.f;
        #pragma unroll
        for (int kk = 0; kk < 8; kk++) {
            uint32_t b0 = Ks[(8 * nt + g) * 68 + 8 * kk + t];
            uint32_t b1 = Ks[(8 * nt + g) * 68 + 8 * kk + t + 4];
            mma_tf32(s[nt], qa[kk][0], qa[kk][1], qa[kk][2], qa[kk][3], b0, b1);
        }
    }
    #pragma unroll
    for (int nt = 0; nt < 25; nt++) {
        s[nt][0] *= SCALE; s[nt][1] *= SCALE;
        s[nt][2] *= SCALE; s[nt][3] *= SCALE;
    }
    if (t >= 2) { s[24][0] = s[24][1] = s[24][2] = s[24][3] = -1e30f; }

    float mlo = -1e30f, mhi = -1e30f;
    #pragma unroll
    for (int nt = 0; nt < 25; nt++) {
        mlo = fmaxf(mlo, fmaxf(s[nt][0], s[nt][1]));
        mhi = fmaxf(mhi, fmaxf(s[nt][2], s[nt][3]));
    }
    mlo = fmaxf(mlo, __shfl_xor_sync(0xffffffffu, mlo, 1));
    mlo = fmaxf(mlo, __shfl_xor_sync(0xffffffffu, mlo, 2));
    mhi = fmaxf(mhi, __shfl_xor_sync(0xffffffffu, mhi, 1));
    mhi = fmaxf(mhi, __shfl_xor_sync(0xffffffffu, mhi, 2));

    float slo = 0.f, shi = 0.f;
    #pragma unroll
    for (int nt = 0; nt < 25; nt++) {
        s[nt][0] = __expf(s[nt][0] - mlo); slo += s[nt][0];
        s[nt][1] = __expf(s[nt][1] - mlo); slo += s[nt][1];
        s[nt][2] = __expf(s[nt][2] - mhi); shi += s[nt][2];
        s[nt][3] = __expf(s[nt][3] - mhi); shi += s[nt][3];
    }
    slo += __shfl_xor_sync(0xffffffffu, slo, 1);
    slo += __shfl_xor_sync(0xffffffffu, slo, 2);
    shi += __shfl_xor_sync(0xffffffffu, shi, 1);
    shi += __shfl_xor_sync(0xffffffffu, shi, 2);
    float rlo = 1.f / slo, rhi = 1.f / shi;
    #pragma unroll
    for (int nt = 0; nt < 25; nt++) {
        s[nt][0] *= rlo; s[nt][1] *= rlo;
        s[nt][2] *= rhi; s[nt][3] *= rhi;
    }

    float o[8][4];
    #pragma unroll
    for (int n = 0; n < 8; n++)
        o[n][0] = o[n][1] = o[n][2] = o[n][3] = 0.f;

    const int src0 = (lane & ~3) | (t >> 1);
    const int src1 = src0 | 2;

    #pragma unroll
    for (int kk = 0; kk < 25; kk++) {
        float x0 = __shfl_sync(0xffffffffu, s[kk][0], src0);
        float x1 = __shfl_sync(0xffffffffu, s[kk][1], src0);
        float x2 = __shfl_sync(0xffffffffu, s[kk][2], src0);
        float x3 = __shfl_sync(0xffffffffu, s[kk][3], src0);
        float y0 = __shfl_sync(0xffffffffu, s[kk][0], src1);
        float y1 = __shfl_sync(0xffffffffu, s[kk][1], src1);
        float y2 = __shfl_sync(0xffffffffu, s[kk][2], src1);
        float y3 = __shfl_sync(0xffffffffu, s[kk][3], src1);
        uint32_t pa0 = f2tf32((t & 1) ? x1 : x0);
        uint32_t pa1 = f2tf32((t & 1) ? x3 : x2);
        uint32_t pa2 = f2tf32((t & 1) ? y1 : y0);
        uint32_t pa3 = f2tf32((t & 1) ? y3 : y2);
        #pragma unroll
        for (int n = 0; n < 8; n++) {
            uint32_t b0 = Vs[(8 * kk + t) * 72 + 8 * n + g];
            uint32_t b1 = Vs[(8 * kk + t + 4) * 72 + 8 * n + g];
            mma_tf32(o[n], pa0, pa1, pa2, pa3, b0, b1);
        }
    }

    const int r1 = qt * 128 + q0 + g;
    const int r2 = r1 + 8;
    #pragma unroll
    for (int n = 0; n < 8; n++) {
        int c = head * D_ + 8 * n + 2 * t;
        float* p1 = g_traj + ((size_t)(b * S_ + r1) * F_ + f) * C_ + c;
        p1[0] = roundtf32(o[n][0]); p1[1] = roundtf32(o[n][1]);
        float* p2 = g_traj + ((size_t)(b * S_ + r2) * F_ + f) * C_ + c;
        p2[0] = roundtf32(o[n][2]); p2[1] = roundtf32(o[n][3]);
    }
}

// ======================================================================
// CLS attention (stores tf32-rounded)
// ======================================================================
__global__ __launch_bounds__(256) void cls_attn_kernel()
{
    __shared__ float sims[N_];
    __shared__ float q0s[64];
    __shared__ float red[9];

    const int bh   = blockIdx.x;
    const int b    = bh / H_;
    const int head = bh % H_;
    const int tid  = threadIdx.x;
    const int w    = tid >> 5;
    const int lane = tid & 31;

    const float* base = g_qkv + (size_t)b * N_ * C3_;

    if (tid < 64) q0s[tid] = base[head * D_ + tid];
    __syncthreads();

    for (int j = tid; j < N_; j += 256) {
        const float* kr = base + (size_t)j * C3_ + C_ + head * D_;
        float dsum = 0.f;
        #pragma unroll
        for (int di = 0; di < 64; di += 4) {
            float4 kv = *(const float4*)(kr + di);
            dsum += q0s[di] * kv.x + q0s[di + 1] * kv.y
                  + q0s[di + 2] * kv.z + q0s[di + 3] * kv.w;
        }
        sims[j] = dsum * SCALE;
    }
    __syncthreads();

    float m = -1e30f;
    for (int j = tid; j < N_; j += 256) m = fmaxf(m, sims[j]);
    #pragma unroll
    for (int off = 16; off; off >>= 1) m = fmaxf(m, __shfl_xor_sync(0xffffffffu, m, off));
    if (lane == 0) red[w] = m;
    __syncthreads();
    if (tid == 0) {
        float mm = red[0];
        #pragma unroll
        for (int i = 1; i < 8; i++) mm = fmaxf(mm, red[i]);
        red[8] = mm;
    }
    __syncthreads();
    const float M = red[8];
    __syncthreads();

    float ls = 0.f;
    for (int j = tid; j < N_; j += 256) {
        float p = __expf(sims[j] - M);
        sims[j] = p;
        ls += p;
    }
    #pragma unroll
    for (int off = 16; off; off >>= 1) ls += __shfl_xor_sync(0xffffffffu, ls, off);
    if (lane == 0) red[w] = ls;
    __syncthreads();
    if (tid == 0) {
        float ss = 0.f;
        #pragma unroll
        for (int i = 0; i < 8; i++) ss += red[i];
        red[8] = ss;
    }
    __syncthreads();
    const float SUM = red[8];

    if (tid < 64) {
        float acc = 0.f;
        const float* vcol = base + 2 * C_ + head * D_ + tid;
        #pragma unroll 4
        for (int j = 0; j < N_; j++)
            acc += sims[j] * vcol[(size_t)j * C3_];
        g_attin[(size_t)b * N_ * C_ + head * D_ + tid] = roundtf32(acc / SUM);
    }
}

// ======================================================================
// Final frame attention (stores tf32-rounded into g_attin)
// ======================================================================
__global__ __launch_bounds__(256) void final_attn_kernel(float* __restrict__ attn_out)
{
    int gw   = (blockIdx.x * 256 + threadIdx.x) >> 5;
    int lane = threadIdx.x & 31;
    if (gw >= B_ * H_ * S_) return;
    int b    = gw / (H_ * S_);
    int r    = gw % (H_ * S_);
    int head = r / S_;
    int s    = r % S_;

    const float* q2p = g_q2 + ((size_t)b * S_ + s) * C_ + head * D_;
    float q0 = q2p[lane];
    float q1 = q2p[lane + 32];

    const float* k2p = g_k2 + ((size_t)b * S_ + s) * (size_t)F_ * C_ + head * D_;
    float lg[8];
    #pragma unroll
    for (int f = 0; f < 8; f++) {
        float tt = q0 * k2p[f * C_ + lane] + q1 * k2p[f * C_ + lane + 32];
        #pragma unroll
        for (int off = 16; off; off >>= 1)
            tt += __shfl_xor_sync(0xffffffffu, tt, off);
        lg[f] = tt;
    }
    float m = lg[0];
    #pragma unroll
    for (int f = 1; f < 8; f++) m = fmaxf(m, lg[f]);
    float p[8], sum = 0.f;
    #pragma unroll
    for (int f = 0; f < 8; f++) { p[f] = __expf(lg[f] - m); sum += p[f]; }
    float inv = 1.f / sum;

    float* ap = attn_out + (((size_t)b * H_ + head) * S_ + s) * F_;
    #pragma unroll
    for (int f = 0; f < 8; f++)
        if (lane == f) ap[f] = p[f] * inv;

    const float* tp = g_traj + ((size_t)b * S_ + s) * (size_t)F_ * C_ + head * D_;
    float o0 = 0.f, o1 = 0.f;
    #pragma unroll
    for (int f = 0; f < 8; f++) {
        float pf = p[f] * inv;
        o0 += pf * tp[f * C_ + lane];
        o1 += pf * tp[f * C_ + lane + 32];
    }
    float* op = g_attin + ((size_t)b * N_ + 1 + s) * C_ + head * D_;
    op[lane]      = roundtf32(o0);
    op[lane + 32] = roundtf32(o1);
}

// ======================================================================
// Host launcher
// ======================================================================
extern "C" void kernel_launch(void* const* d_in, const int* in_sizes, int n_in,
                              void* d_out, int out_size)
{
    const float* x      = (const float*)d_in[0];
    const float* W_qkv  = (const float*)d_in[1];
    const float* W_pq   = (const float*)d_in[2];
    const float* W_pkv  = (const float*)d_in[3];
    const float* W_proj = (const float*)d_in[4];
    const float* b_proj = (const float*)d_in[5];

    float* out  = (float*)d_out;
    float* attn = out + (size_t)B_ * N_ * C_;

    float *qkv, *traj, *q2, *k2, *attin;
    float *xr, *wqkvr, *wpqr, *wpkvr, *wprojr;
    cudaGetSymbolAddress((void**)&qkv,   g_qkv);
    cudaGetSymbolAddress((void**)&traj,  g_traj);
    cudaGetSymbolAddress((void**)&q2,    g_q2);
    cudaGetSymbolAddress((void**)&k2,    g_k2);
    cudaGetSymbolAddress((void**)&attin, g_attin);
    cudaGetSymbolAddress((void**)&xr,     g_xr);
    cudaGetSymbolAddress((void**)&wqkvr,  g_wqkvr);
    cudaGetSymbolAddress((void**)&wpqr,   g_wpqr);
    cudaGetSymbolAddress((void**)&wpkvr,  g_wpkvr);
    cudaGetSymbolAddress((void**)&wprojr, g_wprojr);

    cudaFuncSetAttribute(gemm_tf32_db,
                         cudaFuncAttributeMaxDynamicSharedMemorySize, GEMM_SMEM_BYTES);
    cudaFuncSetAttribute(space_attn_mma,
                         cudaFuncAttributeMaxDynamicSharedMemorySize, SAT_SMEM_BYTES);

    // 0) pre-round external GEMM operands to tf32 (rna), once
    round_tf32_kernel<<<(B_*N_*C_/4 + 255)/256, 256>>>(x,      xr,     B_*N_*C_);
    round_tf32_kernel<<<(C_*C3_ /4 + 255)/256, 256>>>(W_qkv,  wqkvr,  C_*C3_);
    round_tf32_kernel<<<(C_*C_  /4 + 255)/256, 256>>>(W_pq,   wpqr,   C_*C_);
    round_tf32_kernel<<<(C_*2*C_/4 + 255)/256, 256>>>(W_pkv,  wpkvr,  C_*2*C_);
    round_tf32_kernel<<<(C_*C_  /4 + 255)/256, 256>>>(W_proj, wprojr, C_*C_);

    // 1) qkv = x @ W_qkv      (3138 x 2304 x 768)
    gemm_tf32_db<<<dim3(C3_ / 128, (B_ * N_ + 127) / 128), 256, GEMM_SMEM_BYTES>>>(
        xr, C_, wqkvr, C3_, qkv, C3_, B_ * N_, C_, 1.f, nullptr, 0);

    // 2) cls attention -> g_attin rows 0
    cls_attn_kernel<<<B_ * H_, 256>>>();

    // 3) space attention -> g_traj (tensor cores, tf32-rounded stores)
    space_attn_mma<<<dim3(13, F_, B_ * H_), 256, SAT_SMEM_BYTES>>>();

    // 4) q2 = scale * (x_diag @ W_pq)  (diag gather fused into A-load)
    gemm_tf32_db<<<dim3(C_ / 128, (B_ * S_ + 127) / 128), 256, GEMM_SMEM_BYTES>>>(
        traj, 0, wpqr, C_, q2, C_, B_ * S_, C_, SCALE, nullptr, 1);

    // 5) k2 = traj @ W_pkv[:, :C]      (25088 x 768 x 768)  [v2 dead code]
    gemm_tf32_db<<<dim3(C_ / 128, (B_ * S_ * F_) / 128), 256, GEMM_SMEM_BYTES>>>(
        traj, C_, wpkvr, 2 * C_, k2, C_, B_ * S_ * F_, C_, 1.f, nullptr, 0);

    // 6) frame softmax + weighted traj sum -> attn + g_attin rows 1..
    final_attn_kernel<<<(B_ * H_ * S_ * 32) / 256, 256>>>(attn);

    // 7) out = concat(cls, out_pre) @ W_proj + b_proj -> d_out
    gemm_tf32_db<<<dim3(C_ / 128, (B_ * N_ + 127) / 128), 256, GEMM_SMEM_BYTES>>>(
        attin, C_, wprojr, C_, out, C_, B_ * N_, C_, 1.f, b_proj, 0);
}

// round 10
// speedup vs baseline: 2.9874x; 1.0365x over previous
#include <cuda_runtime.h>
#include <cstdint>
#include <cstddef>

// ---------------- problem constants ----------------
#define B_   2
#define N_   1569
#define C_   768
#define H_   12
#define D_   64
#define P_   196
#define F_   8
#define S_   1568          // F_*P_ = N_-1
#define C3_  2304          // 3*C_
#define BS_  (B_*S_)       // 3136
#define SCALE 0.125f       // d^-0.5 = 1/8

// ---------------- scratch (device globals) ----------------
__device__ float g_qkv  [B_*N_*C3_];
__device__ float g_traj [B_*S_*F_*C_];   // tf32-rounded
__device__ float g_q2   [B_*S_*C_];      // tf32-rounded (GEMM epilogue)
__device__ float g_u    [H_*BS_*C_];     // u[h][bs][c]
__device__ float g_attin[B_*N_*C_];      // tf32-rounded
// tf32-rounded operand copies
__device__ float g_xr    [B_*N_*C_];
__device__ float g_wqkvr [C_*C3_];
__device__ float g_wpqr  [C_*C_];
__device__ float g_wkT   [C_*C_];        // WkT[c'][c] = W_pkv[c][c'] (rounded)
__device__ float g_wprojr[C_*C_];

// ---------------- helpers ----------------
__device__ __forceinline__ uint32_t f2tf32(float f) {
    uint32_t o;
    asm("cvt.rna.tf32.f32 %0, %1;" : "=r"(o) : "f"(f));
    return o;
}
__device__ __forceinline__ float roundtf32(float f) {
    return __uint_as_float(f2tf32(f));
}
__device__ __forceinline__ void cp16(void* dst, const void* src, bool p) {
    uint32_t d = (uint32_t)__cvta_generic_to_shared(dst);
    int sz = p ? 16 : 0;
    asm volatile("cp.async.ca.shared.global [%0], [%1], 16, %2;"
                 :: "r"(d), "l"(src), "r"(sz));
}
__device__ __forceinline__ void cp_commit() {
    asm volatile("cp.async.commit_group;");
}
__device__ __forceinline__ void mma_tf32(float* c,
    uint32_t a0, uint32_t a1, uint32_t a2, uint32_t a3,
    uint32_t b0, uint32_t b1)
{
    asm volatile(
        "mma.sync.aligned.m16n8k8.row.col.f32.tf32.tf32.f32 "
        "{%0,%1,%2,%3}, {%4,%5,%6,%7}, {%8,%9}, {%0,%1,%2,%3};"
        : "+f"(c[0]), "+f"(c[1]), "+f"(c[2]), "+f"(c[3])
        : "r"(a0), "r"(a1), "r"(a2), "r"(a3), "r"(b0), "r"(b1));
}

// ======================================================================
// Pre-pass: round to tf32 (rna). n % 4 == 0.
// ======================================================================
__global__ __launch_bounds__(256) void round_tf32_kernel(
    const float* __restrict__ src, float* __restrict__ dst, int n)
{
    int i = (blockIdx.x * 256 + threadIdx.x) * 4;
    if (i >= n) return;
    float4 v = *(const float4*)(src + i);
    v.x = roundtf32(v.x); v.y = roundtf32(v.y);
    v.z = roundtf32(v.z); v.w = roundtf32(v.w);
    *(float4*)(dst + i) = v;
}

// ======================================================================
// Transpose + round: WkT[c'][c] = W_pkv[c][c'] (first C cols of W_pkv).
// 32x32 tiles, blockDim (32,8). Grid (C/32, C/32).
// ======================================================================
__global__ __launch_bounds__(256) void transpose_round_kernel(
    const float* __restrict__ src, float* __restrict__ dst)
{
    __shared__ float tile[32][33];
    int x0 = blockIdx.x * 32;   // source col (c')
    int y0 = blockIdx.y * 32;   // source row (c)
    #pragma unroll
    for (int i = 0; i < 4; i++) {
        int y = y0 + threadIdx.y + i * 8;
        tile[threadIdx.y + i * 8][threadIdx.x] =
            roundtf32(src[(size_t)y * (2 * C_) + x0 + threadIdx.x]);
    }
    __syncthreads();
    #pragma unroll
    for (int i = 0; i < 4; i++) {
        int yo = x0 + threadIdx.y + i * 8;     // dst row = c'
        dst[(size_t)yo * C_ + y0 + threadIdx.x] =
            tile[threadIdx.x][threadIdx.y + i * 8];
    }
}

// ======================================================================
// TF32 GEMM, cp.async double buffered, cvt-free mainloop.
// C[M,N] = alpha * A[M,K] @ B[K,N] (+ bias). BM=BN=128, BK=32, 256 thr.
// flags bit0: diag A-gather (traj row r*F + (r%S)/P).
// flags bit1: round output to tf32.
// z-batch: per blockIdx.z, A += zsa (elems), B += zsb, C += zsc.
// ======================================================================
#define GEMM_SMEM_BYTES ((2*128*36 + 2*32*136) * 4)

__global__ __launch_bounds__(256, 2) void gemm_tf32_db(
    const float* __restrict__ A, int lda,
    const float* __restrict__ Bw, int ldb,
    float* __restrict__ Cc, int ldc,
    int M, int K, float alpha, const float* __restrict__ bias, int flags,
    int zsa, size_t zsb, size_t zsc)
{
    extern __shared__ float gsm[];
    float* As = gsm;                 // [2][128*36]
    float* Bs = gsm + 2 * 128 * 36;  // [2][32*136]

    A  += (size_t)blockIdx.z * zsa;
    Bw += (size_t)blockIdx.z * zsb;
    Cc += (size_t)blockIdx.z * zsc;

    const int tid    = threadIdx.x;
    const int warp   = tid >> 5;
    const int lane   = tid & 31;
    const int g      = lane >> 2;
    const int t      = lane & 3;
    const int warp_m = warp >> 2;
    const int warp_n = warp & 3;
    const int row0   = blockIdx.y * 128;
    const int col0   = blockIdx.x * 128;
    const bool diag  = flags & 1;
    const bool rndo  = flags & 2;

    float acc[4][4][4];
    #pragma unroll
    for (int mt = 0; mt < 4; mt++)
        #pragma unroll
        for (int nt = 0; nt < 4; nt++)
            #pragma unroll
            for (int r = 0; r < 4; r++) acc[mt][nt][r] = 0.f;

    const int ntiles = K / 32;

    auto issue_tile = [&](int buf, int k0) {
        float* Ab = As + buf * 128 * 36;
        float* Bb = Bs + buf * 32 * 136;
        #pragma unroll
        for (int i = 0; i < 4; i++) {
            int idx = tid + i * 256;
            int r   = idx >> 3;
            int c   = (idx & 7) * 4;
            int gr  = row0 + r;
            const float* src;
            if (diag) {
                int s = gr % S_;
                src = A + ((size_t)gr * F_ + (s / P_)) * C_ + k0 + c;
            } else {
                src = A + (size_t)gr * lda + k0 + c;
            }
            cp16(Ab + r * 36 + c, src, gr < M);
        }
        #pragma unroll
        for (int i = 0; i < 4; i++) {
            int idx = tid + i * 256;
            int r   = idx >> 5;
            int c   = (idx & 31) * 4;
            cp16(Bb + r * 136 + c, Bw + (size_t)(k0 + r) * ldb + col0 + c, true);
        }
        cp_commit();
    };

    issue_tile(0, 0);

    for (int kt = 0; kt < ntiles; kt++) {
        int cur = kt & 1;
        if (kt + 1 < ntiles) {
            issue_tile(cur ^ 1, (kt + 1) * 32);
            asm volatile("cp.async.wait_group 1;");
        } else {
            asm volatile("cp.async.wait_group 0;");
        }
        __syncthreads();

        const uint32_t* Ab = (const uint32_t*)(As + cur * 128 * 36);
        const uint32_t* Bb = (const uint32_t*)(Bs + cur * 32 * 136);

        #pragma unroll
        for (int kk = 0; kk < 32; kk += 8) {
            uint32_t a[4][4], bf[4][2];
            #pragma unroll
            for (int mt = 0; mt < 4; mt++) {
                int r = warp_m * 64 + mt * 16 + g;
                const uint32_t* p = &Ab[r * 36 + kk + t];
                a[mt][0] = p[0];
                a[mt][1] = p[8 * 36];
                a[mt][2] = p[4];
                a[mt][3] = p[8 * 36 + 4];
            }
            #pragma unroll
            for (int nt = 0; nt < 4; nt++) {
                int c = warp_n * 32 + nt * 8 + g;
                const uint32_t* p = &Bb[(kk + t) * 136 + c];
                bf[nt][0] = p[0];
                bf[nt][1] = p[4 * 136];
            }
            #pragma unroll
            for (int mt = 0; mt < 4; mt++)
                #pragma unroll
                for (int nt = 0; nt < 4; nt++)
                    mma_tf32(acc[mt][nt], a[mt][0], a[mt][1], a[mt][2], a[mt][3],
                             bf[nt][0], bf[nt][1]);
        }
        __syncthreads();
    }

    #pragma unroll
    for (int nt = 0; nt < 4; nt++) {
        int c = col0 + warp_n * 32 + nt * 8 + t * 2;
        float b0 = bias ? bias[c]     : 0.f;
        float b1 = bias ? bias[c + 1] : 0.f;
        #pragma unroll
        for (int mt = 0; mt < 4; mt++) {
            int r = row0 + warp_m * 64 + mt * 16 + g;
            #pragma unroll
            for (int half = 0; half < 2; half++) {
                int rr = r + half * 8;
                if (rr < M) {
                    float v0 = acc[mt][nt][half * 2 + 0] * alpha + b0;
                    float v1 = acc[mt][nt][half * 2 + 1] * alpha + b1;
                    if (rndo) { v0 = roundtf32(v0); v1 = roundtf32(v1); }
                    float* cp = Cc + (size_t)rr * ldc + c;
                    cp[0] = v0;
                    cp[1] = v1;
                }
            }
        }
    }
}

// ======================================================================
// Space attention on tensor cores (unchanged from R9).
// ======================================================================
#define SAT_SMEM_BYTES ((128*68 + 200*68 + 200*72) * 4)

__global__ __launch_bounds__(256) void space_attn_mma()
{
    extern __shared__ uint32_t ssm[];
    uint32_t* Qs = ssm;                  // [128][68]
    uint32_t* Ks = ssm + 128 * 68;       // [200][68]
    uint32_t* Vs = Ks + 200 * 68;        // [200][72]

    const int qt   = blockIdx.x;
    const int f    = blockIdx.y;
    const int bh   = blockIdx.z;
    const int b    = bh / H_;
    const int head = bh % H_;
    const int tid  = threadIdx.x;
    const int w    = tid >> 5;
    const int lane = tid & 31;
    const int g    = lane >> 2;
    const int t    = lane & 3;

    const float* base = g_qkv + (size_t)b * N_ * C3_;

    #pragma unroll
    for (int i = 0; i < 8; i++) {
        int idx = tid + i * 256;
        int r   = idx >> 4;
        int cf  = (idx & 15) * 4;
        int sq  = qt * 128 + r;
        float4 v = make_float4(0.f, 0.f, 0.f, 0.f);
        if (sq < S_)
            v = *(const float4*)(base + (size_t)(1 + sq) * C3_ + head * D_ + cf);
        uint32_t* d = &Qs[r * 68 + cf];
        d[0] = f2tf32(v.x); d[1] = f2tf32(v.y);
        d[2] = f2tf32(v.z); d[3] = f2tf32(v.w);
    }
    for (int idx = tid; idx < 3200; idx += 256) {
        int r  = idx >> 4;
        int cf = (idx & 15) * 4;
        float4 kv = make_float4(0.f, 0.f, 0.f, 0.f);
        float4 vv = make_float4(0.f, 0.f, 0.f, 0.f);
        if (r < P_) {
            const float* row = base + (size_t)(1 + f * P_ + r) * C3_ + head * D_ + cf;
            kv = *(const float4*)(row + C_);
            vv = *(const float4*)(row + 2 * C_);
        }
        uint32_t* dk = &Ks[r * 68 + cf];
        dk[0] = f2tf32(kv.x); dk[1] = f2tf32(kv.y);
        dk[2] = f2tf32(kv.z); dk[3] = f2tf32(kv.w);
        uint32_t* dv = &Vs[r * 72 + cf];
        dv[0] = f2tf32(vv.x); dv[1] = f2tf32(vv.y);
        dv[2] = f2tf32(vv.z); dv[3] = f2tf32(vv.w);
    }
    __syncthreads();

    const int q0 = w * 16;
    if (qt * 128 + q0 >= S_) return;

    uint32_t qa[8][4];
    #pragma unroll
    for (int kk = 0; kk < 8; kk++) {
        qa[kk][0] = Qs[(q0 + g) * 68 + 8 * kk + t];
        qa[kk][1] = Qs[(q0 + 8 + g) * 68 + 8 * kk + t];
        qa[kk][2] = Qs[(q0 + g) * 68 + 8 * kk + t + 4];
        qa[kk][3] = Qs[(q0 + 8 + g) * 68 + 8 * kk + t + 4];
    }

    float s[25][4];
    #pragma unroll
    for (int nt = 0; nt < 25; nt++) {
        s[nt][0] = s[nt][1] = s[nt][2] = s[nt][3] = 0.f;
        #pragma unroll
        for (int kk = 0; kk < 8; kk++) {
            uint32_t b0 = Ks[(8 * nt + g) * 68 + 8 * kk + t];
            uint32_t b1 = Ks[(8 * nt + g) * 68 + 8 * kk + t + 4];
            mma_tf32(s[nt], qa[kk][0], qa[kk][1], qa[kk][2], qa[kk][3], b0, b1);
        }
    }
    #pragma unroll
    for (int nt = 0; nt < 25; nt++) {
        s[nt][0] *= SCALE; s[nt][1] *= SCALE;
        s[nt][2] *= SCALE; s[nt][3] *= SCALE;
    }
    if (t >= 2) { s[24][0] = s[24][1] = s[24][2] = s[24][3] = -1e30f; }

    float mlo = -1e30f, mhi = -1e30f;
    #pragma unroll
    for (int nt = 0; nt < 25; nt++) {
        mlo = fmaxf(mlo, fmaxf(s[nt][0], s[nt][1]));
        mhi = fmaxf(mhi, fmaxf(s[nt][2], s[nt][3]));
    }
    mlo = fmaxf(mlo, __shfl_xor_sync(0xffffffffu, mlo, 1));
    mlo = fmaxf(mlo, __shfl_xor_sync(0xffffffffu, mlo, 2));
    mhi = fmaxf(mhi, __shfl_xor_sync(0xffffffffu, mhi, 1));
    mhi = fmaxf(mhi, __shfl_xor_sync(0xffffffffu, mhi, 2));

    float slo = 0.f, shi = 0.f;
    #pragma unroll
    for (int nt = 0; nt < 25; nt++) {
        s[nt][0] = __expf(s[nt][0] - mlo); slo += s[nt][0];
        s[nt][1] = __expf(s[nt][1] - mlo); slo += s[nt][1];
        s[nt][2] = __expf(s[nt][2] - mhi); shi += s[nt][2];
        s[nt][3] = __expf(s[nt][3] - mhi); shi += s[nt][3];
    }
    slo += __shfl_xor_sync(0xffffffffu, slo, 1);
    slo += __shfl_xor_sync(0xffffffffu, slo, 2);
    shi += __shfl_xor_sync(0xffffffffu, shi, 1);
    shi += __shfl_xor_sync(0xffffffffu, shi, 2);
    float rlo = 1.f / slo, rhi = 1.f / shi;
    #pragma unroll
    for (int nt = 0; nt < 25; nt++) {
        s[nt][0] *= rlo; s[nt][1] *= rlo;
        s[nt][2] *= rhi; s[nt][3] *= rhi;
    }

    float o[8][4];
    #pragma unroll
    for (int n = 0; n < 8; n++)
        o[n][0] = o[n][1] = o[n][2] = o[n][3] = 0.f;

    const int src0 = (lane & ~3) | (t >> 1);
    const int src1 = src0 | 2;

    #pragma unroll
    for (int kk = 0; kk < 25; kk++) {
        float x0 = __shfl_sync(0xffffffffu, s[kk][0], src0);
        float x1 = __shfl_sync(0xffffffffu, s[kk][1], src0);
        float x2 = __shfl_sync(0xffffffffu, s[kk][2], src0);
        float x3 = __shfl_sync(0xffffffffu, s[kk][3], src0);
        float y0 = __shfl_sync(0xffffffffu, s[kk][0], src1);
        float y1 = __shfl_sync(0xffffffffu, s[kk][1], src1);
        float y2 = __shfl_sync(0xffffffffu, s[kk][2], src1);
        float y3 = __shfl_sync(0xffffffffu, s[kk][3], src1);
        uint32_t pa0 = f2tf32((t & 1) ? x1 : x0);
        uint32_t pa1 = f2tf32((t & 1) ? x3 : x2);
        uint32_t pa2 = f2tf32((t & 1) ? y1 : y0);
        uint32_t pa3 = f2tf32((t & 1) ? y3 : y2);
        #pragma unroll
        for (int n = 0; n < 8; n++) {
            uint32_t b0 = Vs[(8 * kk + t) * 72 + 8 * n + g];
            uint32_t b1 = Vs[(8 * kk + t + 4) * 72 + 8 * n + g];
            mma_tf32(o[n], pa0, pa1, pa2, pa3, b0, b1);
        }
    }

    const int r1 = qt * 128 + q0 + g;
    const int r2 = r1 + 8;
    #pragma unroll
    for (int n = 0; n < 8; n++) {
        int c = head * D_ + 8 * n + 2 * t;
        float* p1 = g_traj + ((size_t)(b * S_ + r1) * F_ + f) * C_ + c;
        p1[0] = roundtf32(o[n][0]); p1[1] = roundtf32(o[n][1]);
        float* p2 = g_traj + ((size_t)(b * S_ + r2) * F_ + f) * C_ + c;
        p2[0] = roundtf32(o[n][2]); p2[1] = roundtf32(o[n][3]);
    }
}

// ======================================================================
// CLS attention (unchanged)
// ======================================================================
__global__ __launch_bounds__(256) void cls_attn_kernel()
{
    __shared__ float sims[N_];
    __shared__ float q0s[64];
    __shared__ float red[9];

    const int bh   = blockIdx.x;
    const int b    = bh / H_;
    const int head = bh % H_;
    const int tid  = threadIdx.x;
    const int w    = tid >> 5;
    const int lane = tid & 31;

    const float* base = g_qkv + (size_t)b * N_ * C3_;

    if (tid < 64) q0s[tid] = base[head * D_ + tid];
    __syncthreads();

    for (int j = tid; j < N_; j += 256) {
        const float* kr = base + (size_t)j * C3_ + C_ + head * D_;
        float dsum = 0.f;
        #pragma unroll
        for (int di = 0; di < 64; di += 4) {
            float4 kv = *(const float4*)(kr + di);
            dsum += q0s[di] * kv.x + q0s[di + 1] * kv.y
                  + q0s[di + 2] * kv.z + q0s[di + 3] * kv.w;
        }
        sims[j] = dsum * SCALE;
    }
    __syncthreads();

    float m = -1e30f;
    for (int j = tid; j < N_; j += 256) m = fmaxf(m, sims[j]);
    #pragma unroll
    for (int off = 16; off; off >>= 1) m = fmaxf(m, __shfl_xor_sync(0xffffffffu, m, off));
    if (lane == 0) red[w] = m;
    __syncthreads();
    if (tid == 0) {
        float mm = red[0];
        #pragma unroll
        for (int i = 1; i < 8; i++) mm = fmaxf(mm, red[i]);
        red[8] = mm;
    }
    __syncthreads();
    const float M = red[8];
    __syncthreads();

    float ls = 0.f;
    for (int j = tid; j < N_; j += 256) {
        float p = __expf(sims[j] - M);
        sims[j] = p;
        ls += p;
    }
    #pragma unroll
    for (int off = 16; off; off >>= 1) ls += __shfl_xor_sync(0xffffffffu, ls, off);
    if (lane == 0) red[w] = ls;
    __syncthreads();
    if (tid == 0) {
        float ss = 0.f;
        #pragma unroll
        for (int i = 0; i < 8; i++) ss += red[i];
        red[8] = ss;
    }
    __syncthreads();
    const float SUM = red[8];

    if (tid < 64) {
        float acc = 0.f;
        const float* vcol = base + 2 * C_ + head * D_ + tid;
        #pragma unroll 4
        for (int j = 0; j < N_; j++)
            acc += sims[j] * vcol[(size_t)j * C3_];
        g_attin[(size_t)b * N_ * C_ + head * D_ + tid] = roundtf32(acc / SUM);
    }
}

// ======================================================================
// Final frame attention v2: one block per (b,s).
// logits(f,h) = sum_c traj[s,f,c] * u[s,h,c]   (u = per-head Q2@Wk^T)
// Writes attn (B,h,S,F) and projected-input rows of g_attin.
// ======================================================================
__global__ __launch_bounds__(256) void final_attn2_kernel(float* __restrict__ attn_out)
{
    __shared__ float trajs[F_ * C_];   // 6144 floats
    __shared__ float lg[H_ * F_];      // 96 logits [h][f]
    __shared__ float pw[H_ * F_];      // softmax weights

    const int bs   = blockIdx.x;       // 0..BS-1
    const int b    = bs / S_;
    const int s    = bs % S_;
    const int tid  = threadIdx.x;
    const int w    = tid >> 5;
    const int lane = tid & 31;

    // stage traj_s
    const float* tsrc = g_traj + (size_t)bs * F_ * C_;
    #pragma unroll
    for (int i = 0; i < 6; i++) {
        int idx = (tid + i * 256) * 4;
        *(float4*)(trajs + idx) = *(const float4*)(tsrc + idx);
    }
    __syncthreads();

    // logits: 96 (h,f) pairs, one warp each, 12 per warp
    for (int pi = w; pi < H_ * F_; pi += 8) {
        int h = pi >> 3;       // /F_
        int f = pi & 7;
        const float* up = g_u + ((size_t)h * BS_ + bs) * C_;
        const float* tp = trajs + f * C_;
        float acc = 0.f;
        #pragma unroll
        for (int j = 0; j < C_ / 32; j++)
            acc += tp[lane + 32 * j] * up[lane + 32 * j];
        #pragma unroll
        for (int off = 16; off; off >>= 1)
            acc += __shfl_xor_sync(0xffffffffu, acc, off);
        if (lane == 0) lg[pi] = acc;
    }
    __syncthreads();

    // per-head softmax over F (threads 0..11)
    if (tid < H_) {
        float m = lg[tid * F_];
        #pragma unroll
        for (int f = 1; f < F_; f++) m = fmaxf(m, lg[tid * F_ + f]);
        float p[F_], sum = 0.f;
        #pragma unroll
        for (int f = 0; f < F_; f++) { p[f] = __expf(lg[tid * F_ + f] - m); sum += p[f]; }
        float inv = 1.f / sum;
        float* ap = attn_out + (((size_t)b * H_ + tid) * S_ + s) * F_;
        #pragma unroll
        for (int f = 0; f < F_; f++) {
            float v = p[f] * inv;
            pw[tid * F_ + f] = v;
            ap[f] = v;
        }
    }
    __syncthreads();

    // out[s, c] = sum_f pw[h(c)][f] * traj[s,f,c]
    float* op = g_attin + ((size_t)b * N_ + 1 + s) * C_;
    #pragma unroll
    for (int i = 0; i < 3; i++) {
        int c = tid + i * 256;
        int h = c >> 6;
        float acc = 0.f;
        #pragma unroll
        for (int f = 0; f < F_; f++)
            acc += pw[h * F_ + f] * trajs[f * C_ + c];
        op[c] = roundtf32(acc);
    }
}

// ======================================================================
// Host launcher
// ======================================================================
extern "C" void kernel_launch(void* const* d_in, const int* in_sizes, int n_in,
                              void* d_out, int out_size)
{
    const float* x      = (const float*)d_in[0];
    const float* W_qkv  = (const float*)d_in[1];
    const float* W_pq   = (const float*)d_in[2];
    const float* W_pkv  = (const float*)d_in[3];
    const float* W_proj = (const float*)d_in[4];
    const float* b_proj = (const float*)d_in[5];

    float* out  = (float*)d_out;
    float* attn = out + (size_t)B_ * N_ * C_;

    float *qkv, *traj, *q2, *u, *attin;
    float *xr, *wqkvr, *wpqr, *wkT, *wprojr;
    cudaGetSymbolAddress((void**)&qkv,   g_qkv);
    cudaGetSymbolAddress((void**)&traj,  g_traj);
    cudaGetSymbolAddress((void**)&q2,    g_q2);
    cudaGetSymbolAddress((void**)&u,     g_u);
    cudaGetSymbolAddress((void**)&attin, g_attin);
    cudaGetSymbolAddress((void**)&xr,     g_xr);
    cudaGetSymbolAddress((void**)&wqkvr,  g_wqkvr);
    cudaGetSymbolAddress((void**)&wpqr,   g_wpqr);
    cudaGetSymbolAddress((void**)&wkT,    g_wkT);
    cudaGetSymbolAddress((void**)&wprojr, g_wprojr);

    cudaFuncSetAttribute(gemm_tf32_db,
                         cudaFuncAttributeMaxDynamicSharedMemorySize, GEMM_SMEM_BYTES);
    cudaFuncSetAttribute(space_attn_mma,
                         cudaFuncAttributeMaxDynamicSharedMemorySize, SAT_SMEM_BYTES);

    // 0) operand prep (round to tf32; transpose Wk)
    round_tf32_kernel<<<(B_*N_*C_/4 + 255)/256, 256>>>(x,      xr,     B_*N_*C_);
    round_tf32_kernel<<<(C_*C3_ /4 + 255)/256, 256>>>(W_qkv,  wqkvr,  C_*C3_);
    round_tf32_kernel<<<(C_*C_  /4 + 255)/256, 256>>>(W_pq,   wpqr,   C_*C_);
    round_tf32_kernel<<<(C_*C_  /4 + 255)/256, 256>>>(W_proj, wprojr, C_*C_);
    transpose_round_kernel<<<dim3(C_/32, C_/32), dim3(32, 8)>>>(W_pkv, wkT);

    // 1) qkv = x @ W_qkv      (3138 x 2304 x 768)
    gemm_tf32_db<<<dim3(C3_/128, (B_*N_ + 127)/128), 256, GEMM_SMEM_BYTES>>>(
        xr, C_, wqkvr, C3_, qkv, C3_, B_*N_, C_, 1.f, nullptr, 0, 0, 0, 0);

    // 2) cls attention -> g_attin rows 0
    cls_attn_kernel<<<B_ * H_, 256>>>();

    // 3) space attention -> g_traj (tensor cores)
    space_attn_mma<<<dim3(13, F_, B_ * H_), 256, SAT_SMEM_BYTES>>>();

    // 4) q2 = scale * (x_diag @ W_pq), tf32-rounded output (diag gather fused)
    gemm_tf32_db<<<dim3(C_/128, (BS_ + 127)/128), 256, GEMM_SMEM_BYTES>>>(
        traj, 0, wpqr, C_, q2, C_, BS_, C_, SCALE, nullptr, 1 | 2, 0, 0, 0);

    // 5) U_h = Q2_h @ WkT_h   (12 z-batched GEMMs, 3136 x 768 x 64)
    gemm_tf32_db<<<dim3(C_/128, (BS_ + 127)/128, H_), 256, GEMM_SMEM_BYTES>>>(
        q2, C_, wkT, C_, u, C_, BS_, D_, 1.f, nullptr, 0,
        D_, (size_t)D_ * C_, (size_t)BS_ * C_);

    // 6) frame logits via traj·u, softmax, weighted traj sum
    final_attn2_kernel<<<BS_, 256>>>(attn);

    // 7) out = concat(cls, out_pre) @ W_proj + b_proj -> d_out
    gemm_tf32_db<<<dim3(C_/128, (B_*N_ + 127)/128), 256, GEMM_SMEM_BYTES>>>(
        attin, C_, wprojr, C_, out, C_, B_*N_, C_, 1.f, b_proj, 0, 0, 0, 0);
}

// round 12
// speedup vs baseline: 3.5788x; 1.1980x over previous
#include <cuda_runtime.h>
#include <cstdint>
#include <cstddef>

// ---------------- problem constants ----------------
#define B_   2
#define N_   1569
#define C_   768
#define H_   12
#define D_   64
#define P_   196
#define F_   8
#define S_   1568          // F_*P_ = N_-1
#define C3_  2304          // 3*C_
#define BS_  (B_*S_)       // 3136
#define SCALE 0.125f       // d^-0.5 = 1/8

// ---------------- scratch (device globals) ----------------
__device__ float g_qkv  [B_*N_*C3_];
__device__ float g_traj [B_*S_*F_*C_];   // tf32-rounded
__device__ float g_q2   [B_*S_*C_];      // tf32-rounded (GEMM epilogue)
__device__ float g_u    [BS_*H_*C_];     // u[bs][h*C+c]  (contiguous per bs)
__device__ float g_attin[B_*N_*C_];      // tf32-rounded
// tf32-rounded operand copies
__device__ float g_xr    [B_*N_*C_];
__device__ float g_wqkvr [C_*C3_];
__device__ float g_wpqr  [C_*C_];
__device__ float g_wkT   [C_*C_];        // WkT[c'][c] = W_pkv[c][c'] (rounded)
__device__ float g_wprojr[C_*C_];

// ---------------- helpers ----------------
__device__ __forceinline__ uint32_t f2tf32(float f) {
    uint32_t o;
    asm("cvt.rna.tf32.f32 %0, %1;" : "=r"(o) : "f"(f));
    return o;
}
__device__ __forceinline__ float roundtf32(float f) {
    return __uint_as_float(f2tf32(f));
}
__device__ __forceinline__ void cp16(void* dst, const void* src, bool p) {
    uint32_t d = (uint32_t)__cvta_generic_to_shared(dst);
    int sz = p ? 16 : 0;
    asm volatile("cp.async.ca.shared.global [%0], [%1], 16, %2;"
                 :: "r"(d), "l"(src), "r"(sz));
}
__device__ __forceinline__ void cp_commit() {
    asm volatile("cp.async.commit_group;");
}
__device__ __forceinline__ void mma_tf32(float* c,
    uint32_t a0, uint32_t a1, uint32_t a2, uint32_t a3,
    uint32_t b0, uint32_t b1)
{
    asm volatile(
        "mma.sync.aligned.m16n8k8.row.col.f32.tf32.tf32.f32 "
        "{%0,%1,%2,%3}, {%4,%5,%6,%7}, {%8,%9}, {%0,%1,%2,%3};"
        : "+f"(c[0]), "+f"(c[1]), "+f"(c[2]), "+f"(c[3])
        : "r"(a0), "r"(a1), "r"(a2), "r"(a3), "r"(b0), "r"(b1));
}

// ======================================================================
// Pre-pass: round to tf32 (rna). n % 4 == 0.
// ======================================================================
__global__ __launch_bounds__(256) void round_tf32_kernel(
    const float* __restrict__ src, float* __restrict__ dst, int n)
{
    int i = (blockIdx.x * 256 + threadIdx.x) * 4;
    if (i >= n) return;
    float4 v = *(const float4*)(src + i);
    v.x = roundtf32(v.x); v.y = roundtf32(v.y);
    v.z = roundtf32(v.z); v.w = roundtf32(v.w);
    *(float4*)(dst + i) = v;
}

// ======================================================================
// Transpose + round: WkT[c'][c] = W_pkv[c][c'] (first C cols of W_pkv).
// ======================================================================
__global__ __launch_bounds__(256) void transpose_round_kernel(
    const float* __restrict__ src, float* __restrict__ dst)
{
    __shared__ float tile[32][33];
    int x0 = blockIdx.x * 32;
    int y0 = blockIdx.y * 32;
    #pragma unroll
    for (int i = 0; i < 4; i++) {
        int y = y0 + threadIdx.y + i * 8;
        tile[threadIdx.y + i * 8][threadIdx.x] =
            roundtf32(src[(size_t)y * (2 * C_) + x0 + threadIdx.x]);
    }
    __syncthreads();
    #pragma unroll
    for (int i = 0; i < 4; i++) {
        int yo = x0 + threadIdx.y + i * 8;
        dst[(size_t)yo * C_ + y0 + threadIdx.x] =
            tile[threadIdx.x][threadIdx.y + i * 8];
    }
}

// ======================================================================
// TF32 GEMM, cp.async double buffered, cvt-free mainloop.
// flags bit0: diag A-gather; bit1: round output to tf32.
// z-batch: A += z*zsa (elems), B += z*zsb, C += z*zsc (zsc may act as a
// column offset when ldc spans multiple head blocks).
// ======================================================================
#define GEMM_SMEM_BYTES ((2*128*36 + 2*32*136) * 4)

__global__ __launch_bounds__(256, 2) void gemm_tf32_db(
    const float* __restrict__ A, int lda,
    const float* __restrict__ Bw, int ldb,
    float* __restrict__ Cc, int ldc,
    int M, int K, float alpha, const float* __restrict__ bias, int flags,
    int zsa, size_t zsb, size_t zsc)
{
    extern __shared__ float gsm[];
    float* As = gsm;                 // [2][128*36]
    float* Bs = gsm + 2 * 128 * 36;  // [2][32*136]

    A  += (size_t)blockIdx.z * zsa;
    Bw += (size_t)blockIdx.z * zsb;
    Cc += (size_t)blockIdx.z * zsc;

    const int tid    = threadIdx.x;
    const int warp   = tid >> 5;
    const int lane   = tid & 31;
    const int g      = lane >> 2;
    const int t      = lane & 3;
    const int warp_m = warp >> 2;
    const int warp_n = warp & 3;
    const int row0   = blockIdx.y * 128;
    const int col0   = blockIdx.x * 128;
    const bool diag  = flags & 1;
    const bool rndo  = flags & 2;

    float acc[4][4][4];
    #pragma unroll
    for (int mt = 0; mt < 4; mt++)
        #pragma unroll
        for (int nt = 0; nt < 4; nt++)
            #pragma unroll
            for (int r = 0; r < 4; r++) acc[mt][nt][r] = 0.f;

    const int ntiles = K / 32;

    auto issue_tile = [&](int buf, int k0) {
        float* Ab = As + buf * 128 * 36;
        float* Bb = Bs + buf * 32 * 136;
        #pragma unroll
        for (int i = 0; i < 4; i++) {
            int idx = tid + i * 256;
            int r   = idx >> 3;
            int c   = (idx & 7) * 4;
            int gr  = row0 + r;
            const float* src;
            if (diag) {
                int s = gr % S_;
                src = A + ((size_t)gr * F_ + (s / P_)) * C_ + k0 + c;
            } else {
                src = A + (size_t)gr * lda + k0 + c;
            }
            cp16(Ab + r * 36 + c, src, gr < M);
        }
        #pragma unroll
        for (int i = 0; i < 4; i++) {
            int idx = tid + i * 256;
            int r   = idx >> 5;
            int c   = (idx & 31) * 4;
            cp16(Bb + r * 136 + c, Bw + (size_t)(k0 + r) * ldb + col0 + c, true);
        }
        cp_commit();
    };

    issue_tile(0, 0);

    for (int kt = 0; kt < ntiles; kt++) {
        int cur = kt & 1;
        if (kt + 1 < ntiles) {
            issue_tile(cur ^ 1, (kt + 1) * 32);
            asm volatile("cp.async.wait_group 1;");
        } else {
            asm volatile("cp.async.wait_group 0;");
        }
        __syncthreads();

        const uint32_t* Ab = (const uint32_t*)(As + cur * 128 * 36);
        const uint32_t* Bb = (const uint32_t*)(Bs + cur * 32 * 136);

        #pragma unroll
        for (int kk = 0; kk < 32; kk += 8) {
            uint32_t a[4][4], bf[4][2];
            #pragma unroll
            for (int mt = 0; mt < 4; mt++) {
                int r = warp_m * 64 + mt * 16 + g;
                const uint32_t* p = &Ab[r * 36 + kk + t];
                a[mt][0] = p[0];
                a[mt][1] = p[8 * 36];
                a[mt][2] = p[4];
                a[mt][3] = p[8 * 36 + 4];
            }
            #pragma unroll
            for (int nt = 0; nt < 4; nt++) {
                int c = warp_n * 32 + nt * 8 + g;
                const uint32_t* p = &Bb[(kk + t) * 136 + c];
                bf[nt][0] = p[0];
                bf[nt][1] = p[4 * 136];
            }
            #pragma unroll
            for (int mt = 0; mt < 4; mt++)
                #pragma unroll
                for (int nt = 0; nt < 4; nt++)
                    mma_tf32(acc[mt][nt], a[mt][0], a[mt][1], a[mt][2], a[mt][3],
                             bf[nt][0], bf[nt][1]);
        }
        __syncthreads();
    }

    #pragma unroll
    for (int nt = 0; nt < 4; nt++) {
        int c = col0 + warp_n * 32 + nt * 8 + t * 2;
        float b0 = bias ? bias[c]     : 0.f;
        float b1 = bias ? bias[c + 1] : 0.f;
        #pragma unroll
        for (int mt = 0; mt < 4; mt++) {
            int r = row0 + warp_m * 64 + mt * 16 + g;
            #pragma unroll
            for (int half = 0; half < 2; half++) {
                int rr = r + half * 8;
                if (rr < M) {
                    float v0 = acc[mt][nt][half * 2 + 0] * alpha + b0;
                    float v1 = acc[mt][nt][half * 2 + 1] * alpha + b1;
                    if (rndo) { v0 = roundtf32(v0); v1 = roundtf32(v1); }
                    float* cp = Cc + (size_t)rr * ldc + c;
                    cp[0] = v0;
                    cp[1] = v1;
                }
            }
        }
    }
}

// ======================================================================
// Space attention on tensor cores (unchanged from R10).
// ======================================================================
#define SAT_SMEM_BYTES ((128*68 + 200*68 + 200*72) * 4)

__global__ __launch_bounds__(256) void space_attn_mma()
{
    extern __shared__ uint32_t ssm[];
    uint32_t* Qs = ssm;                  // [128][68]
    uint32_t* Ks = ssm + 128 * 68;       // [200][68]
    uint32_t* Vs = Ks + 200 * 68;        // [200][72]

    const int qt   = blockIdx.x;
    const int f    = blockIdx.y;
    const int bh   = blockIdx.z;
    const int b    = bh / H_;
    const int head = bh % H_;
    const int tid  = threadIdx.x;
    const int w    = tid >> 5;
    const int lane = tid & 31;
    const int g    = lane >> 2;
    const int t    = lane & 3;

    const float* base = g_qkv + (size_t)b * N_ * C3_;

    #pragma unroll
    for (int i = 0; i < 8; i++) {
        int idx = tid + i * 256;
        int r   = idx >> 4;
        int cf  = (idx & 15) * 4;
        int sq  = qt * 128 + r;
        float4 v = make_float4(0.f, 0.f, 0.f, 0.f);
        if (sq < S_)
            v = *(const float4*)(base + (size_t)(1 + sq) * C3_ + head * D_ + cf);
        uint32_t* d = &Qs[r * 68 + cf];
        d[0] = f2tf32(v.x); d[1] = f2tf32(v.y);
        d[2] = f2tf32(v.z); d[3] = f2tf32(v.w);
    }
    for (int idx = tid; idx < 3200; idx += 256) {
        int r  = idx >> 4;
        int cf = (idx & 15) * 4;
        float4 kv = make_float4(0.f, 0.f, 0.f, 0.f);
        float4 vv = make_float4(0.f, 0.f, 0.f, 0.f);
        if (r < P_) {
            const float* row = base + (size_t)(1 + f * P_ + r) * C3_ + head * D_ + cf;
            kv = *(const float4*)(row + C_);
            vv = *(const float4*)(row + 2 * C_);
        }
        uint32_t* dk = &Ks[r * 68 + cf];
        dk[0] = f2tf32(kv.x); dk[1] = f2tf32(kv.y);
        dk[2] = f2tf32(kv.z); dk[3] = f2tf32(kv.w);
        uint32_t* dv = &Vs[r * 72 + cf];
        dv[0] = f2tf32(vv.x); dv[1] = f2tf32(vv.y);
        dv[2] = f2tf32(vv.z); dv[3] = f2tf32(vv.w);
    }
    __syncthreads();

    const int q0 = w * 16;
    if (qt * 128 + q0 >= S_) return;

    uint32_t qa[8][4];
    #pragma unroll
    for (int kk = 0; kk < 8; kk++) {
        qa[kk][0] = Qs[(q0 + g) * 68 + 8 * kk + t];
        qa[kk][1] = Qs[(q0 + 8 + g) * 68 + 8 * kk + t];
        qa[kk][2] = Qs[(q0 + g) * 68 + 8 * kk + t + 4];
        qa[kk][3] = Qs[(q0 + 8 + g) * 68 + 8 * kk + t + 4];
    }

    float s[25][4];
    #pragma unroll
    for (int nt = 0; nt < 25; nt++) {
        s[nt][0] = s[nt][1] = s[nt][2] = s[nt][3] = 0.f;
        #pragma unroll
        for (int kk = 0; kk < 8; kk++) {
            uint32_t b0 = Ks[(8 * nt + g) * 68 + 8 * kk + t];
            uint32_t b1 = Ks[(8 * nt + g) * 68 + 8 * kk + t + 4];
            mma_tf32(s[nt], qa[kk][0], qa[kk][1], qa[kk][2], qa[kk][3], b0, b1);
        }
    }
    #pragma unroll
    for (int nt = 0; nt < 25; nt++) {
        s[nt][0] *= SCALE; s[nt][1] *= SCALE;
        s[nt][2] *= SCALE; s[nt][3] *= SCALE;
    }
    if (t >= 2) { s[24][0] = s[24][1] = s[24][2] = s[24][3] = -1e30f; }

    float mlo = -1e30f, mhi = -1e30f;
    #pragma unroll
    for (int nt = 0; nt < 25; nt++) {
        mlo = fmaxf(mlo, fmaxf(s[nt][0], s[nt][1]));
        mhi = fmaxf(mhi, fmaxf(s[nt][2], s[nt][3]));
    }
    mlo = fmaxf(mlo, __shfl_xor_sync(0xffffffffu, mlo, 1));
    mlo = fmaxf(mlo, __shfl_xor_sync(0xffffffffu, mlo, 2));
    mhi = fmaxf(mhi, __shfl_xor_sync(0xffffffffu, mhi, 1));
    mhi = fmaxf(mhi, __shfl_xor_sync(0xffffffffu, mhi, 2));

    float slo = 0.f, shi = 0.f;
    #pragma unroll
    for (int nt = 0; nt < 25; nt++) {
        s[nt][0] = __expf(s[nt][0] - mlo); slo += s[nt][0];
        s[nt][1] = __expf(s[nt][1] - mlo); slo += s[nt][1];
        s[nt][2] = __expf(s[nt][2] - mhi); shi += s[nt][2];
        s[nt][3] = __expf(s[nt][3] - mhi); shi += s[nt][3];
    }
    slo += __shfl_xor_sync(0xffffffffu, slo, 1);
    slo += __shfl_xor_sync(0xffffffffu, slo, 2);
    shi += __shfl_xor_sync(0xffffffffu, shi, 1);
    shi += __shfl_xor_sync(0xffffffffu, shi, 2);
    float rlo = 1.f / slo, rhi = 1.f / shi;
    #pragma unroll
    for (int nt = 0; nt < 25; nt++) {
        s[nt][0] *= rlo; s[nt][1] *= rlo;
        s[nt][2] *= rhi; s[nt][3] *= rhi;
    }

    float o[8][4];
    #pragma unroll
    for (int n = 0; n < 8; n++)
        o[n][0] = o[n][1] = o[n][2] = o[n][3] = 0.f;

    const int src0 = (lane & ~3) | (t >> 1);
    const int src1 = src0 | 2;

    #pragma unroll
    for (int kk = 0; kk < 25; kk++) {
        float x0 = __shfl_sync(0xffffffffu, s[kk][0], src0);
        float x1 = __shfl_sync(0xffffffffu, s[kk][1], src0);
        float x2 = __shfl_sync(0xffffffffu, s[kk][2], src0);
        float x3 = __shfl_sync(0xffffffffu, s[kk][3], src0);
        float y0 = __shfl_sync(0xffffffffu, s[kk][0], src1);
        float y1 = __shfl_sync(0xffffffffu, s[kk][1], src1);
        float y2 = __shfl_sync(0xffffffffu, s[kk][2], src1);
        float y3 = __shfl_sync(0xffffffffu, s[kk][3], src1);
        uint32_t pa0 = f2tf32((t & 1) ? x1 : x0);
        uint32_t pa1 = f2tf32((t & 1) ? x3 : x2);
        uint32_t pa2 = f2tf32((t & 1) ? y1 : y0);
        uint32_t pa3 = f2tf32((t & 1) ? y3 : y2);
        #pragma unroll
        for (int n = 0; n < 8; n++) {
            uint32_t b0 = Vs[(8 * kk + t) * 72 + 8 * n + g];
            uint32_t b1 = Vs[(8 * kk + t + 4) * 72 + 8 * n + g];
            mma_tf32(o[n], pa0, pa1, pa2, pa3, b0, b1);
        }
    }

    const int r1 = qt * 128 + q0 + g;
    const int r2 = r1 + 8;
    #pragma unroll
    for (int n = 0; n < 8; n++) {
        int c = head * D_ + 8 * n + 2 * t;
        float* p1 = g_traj + ((size_t)(b * S_ + r1) * F_ + f) * C_ + c;
        p1[0] = roundtf32(o[n][0]); p1[1] = roundtf32(o[n][1]);
        float* p2 = g_traj + ((size_t)(b * S_ + r2) * F_ + f) * C_ + c;
        p2[0] = roundtf32(o[n][2]); p2[1] = roundtf32(o[n][3]);
    }
}

// ======================================================================
// CLS attention (unchanged)
// ======================================================================
__global__ __launch_bounds__(256) void cls_attn_kernel()
{
    __shared__ float sims[N_];
    __shared__ float q0s[64];
    __shared__ float red[9];

    const int bh   = blockIdx.x;
    const int b    = bh / H_;
    const int head = bh % H_;
    const int tid  = threadIdx.x;
    const int w    = tid >> 5;
    const int lane = tid & 31;

    const float* base = g_qkv + (size_t)b * N_ * C3_;

    if (tid < 64) q0s[tid] = base[head * D_ + tid];
    __syncthreads();

    for (int j = tid; j < N_; j += 256) {
        const float* kr = base + (size_t)j * C3_ + C_ + head * D_;
        float dsum = 0.f;
        #pragma unroll
        for (int di = 0; di < 64; di += 4) {
            float4 kv = *(const float4*)(kr + di);
            dsum += q0s[di] * kv.x + q0s[di + 1] * kv.y
                  + q0s[di + 2] * kv.z + q0s[di + 3] * kv.w;
        }
        sims[j] = dsum * SCALE;
    }
    __syncthreads();

    float m = -1e30f;
    for (int j = tid; j < N_; j += 256) m = fmaxf(m, sims[j]);
    #pragma unroll
    for (int off = 16; off; off >>= 1) m = fmaxf(m, __shfl_xor_sync(0xffffffffu, m, off));
    if (lane == 0) red[w] = m;
    __syncthreads();
    if (tid == 0) {
        float mm = red[0];
        #pragma unroll
        for (int i = 1; i < 8; i++) mm = fmaxf(mm, red[i]);
        red[8] = mm;
    }
    __syncthreads();
    const float M = red[8];
    __syncthreads();

    float ls = 0.f;
    for (int j = tid; j < N_; j += 256) {
        float p = __expf(sims[j] - M);
        sims[j] = p;
        ls += p;
    }
    #pragma unroll
    for (int off = 16; off; off >>= 1) ls += __shfl_xor_sync(0xffffffffu, ls, off);
    if (lane == 0) red[w] = ls;
    __syncthreads();
    if (tid == 0) {
        float ss = 0.f;
        #pragma unroll
        for (int i = 0; i < 8; i++) ss += red[i];
        red[8] = ss;
    }
    __syncthreads();
    const float SUM = red[8];

    if (tid < 64) {
        float acc = 0.f;
        const float* vcol = base + 2 * C_ + head * D_ + tid;
        #pragma unroll 4
        for (int j = 0; j < N_; j++)
            acc += sims[j] * vcol[(size_t)j * C3_];
        g_attin[(size_t)b * N_ * C_ + head * D_ + tid] = roundtf32(acc / SUM);
    }
}

// ======================================================================
// Final frame attention v3: one block per (b,s), float4 vectorized.
// u is [bs][h*C+c] (contiguous 36 KB slab per bs).
// ======================================================================
__global__ __launch_bounds__(256) void final_attn2_kernel(float* __restrict__ attn_out)
{
    __shared__ float trajs[F_ * C_];   // 6144 floats
    __shared__ float lg[H_ * F_];
    __shared__ float pw[H_ * F_];

    const int bs   = blockIdx.x;
    const int b    = bs / S_;
    const int s    = bs % S_;
    const int tid  = threadIdx.x;
    const int w    = tid >> 5;
    const int lane = tid & 31;

    const float* tsrc = g_traj + (size_t)bs * F_ * C_;
    #pragma unroll
    for (int i = 0; i < 6; i++) {
        int idx = (tid + i * 256) * 4;
        *(float4*)(trajs + idx) = *(const float4*)(tsrc + idx);
    }
    __syncthreads();

    // logits: 96 (h,f) pairs, 12 per warp, float4 dot products
    const float4* ub = (const float4*)(g_u + (size_t)bs * H_ * C_);
    for (int pi = w; pi < H_ * F_; pi += 8) {
        int h = pi >> 3;
        int f = pi & 7;
        const float4* up = ub + h * (C_ / 4);
        const float4* tp = (const float4*)(trajs + f * C_);
        float acc = 0.f;
        #pragma unroll
        for (int j = 0; j < C_ / 128; j++) {      // 6 iterations
            float4 uv = up[lane + 32 * j];
            float4 tv = tp[lane + 32 * j];
            acc += uv.x * tv.x + uv.y * tv.y + uv.z * tv.z + uv.w * tv.w;
        }
        #pragma unroll
        for (int off = 16; off; off >>= 1)
            acc += __shfl_xor_sync(0xffffffffu, acc, off);
        if (lane == 0) lg[pi] = acc;
    }
    __syncthreads();

    if (tid < H_) {
        float m = lg[tid * F_];
        #pragma unroll
        for (int f = 1; f < F_; f++) m = fmaxf(m, lg[tid * F_ + f]);
        float p[F_], sum = 0.f;
        #pragma unroll
        for (int f = 0; f < F_; f++) { p[f] = __expf(lg[tid * F_ + f] - m); sum += p[f]; }
        float inv = 1.f / sum;
        float* ap = attn_out + (((size_t)b * H_ + tid) * S_ + s) * F_;
        #pragma unroll
        for (int f = 0; f < F_; f++) {
            float v = p[f] * inv;
            pw[tid * F_ + f] = v;
            ap[f] = v;
        }
    }
    __syncthreads();

    float* op = g_attin + ((size_t)b * N_ + 1 + s) * C_;
    #pragma unroll
    for (int i = 0; i < 3; i++) {
        int c = tid + i * 256;
        int h = c >> 6;
        float acc = 0.f;
        #pragma unroll
        for (int f = 0; f < F_; f++)
            acc += pw[h * F_ + f] * trajs[f * C_ + c];
        op[c] = roundtf32(acc);
    }
}

// ======================================================================
// Host launcher — fork/join stream overlap (graph-capture safe)
// ======================================================================
extern "C" void kernel_launch(void* const* d_in, const int* in_sizes, int n_in,
                              void* d_out, int out_size)
{
    const float* x      = (const float*)d_in[0];
    const float* W_qkv  = (const float*)d_in[1];
    const float* W_pq   = (const float*)d_in[2];
    const float* W_pkv  = (const float*)d_in[3];
    const float* W_proj = (const float*)d_in[4];
    const float* b_proj = (const float*)d_in[5];

    float* out  = (float*)d_out;
    float* attn = out + (size_t)B_ * N_ * C_;

    float *qkv, *traj, *q2, *u, *attin;
    float *xr, *wqkvr, *wpqr, *wkT, *wprojr;
    cudaGetSymbolAddress((void**)&qkv,   g_qkv);
    cudaGetSymbolAddress((void**)&traj,  g_traj);
    cudaGetSymbolAddress((void**)&q2,    g_q2);
    cudaGetSymbolAddress((void**)&u,     g_u);
    cudaGetSymbolAddress((void**)&attin, g_attin);
    cudaGetSymbolAddress((void**)&xr,     g_xr);
    cudaGetSymbolAddress((void**)&wqkvr,  g_wqkvr);
    cudaGetSymbolAddress((void**)&wpqr,   g_wpqr);
    cudaGetSymbolAddress((void**)&wkT,    g_wkT);
    cudaGetSymbolAddress((void**)&wprojr, g_wprojr);

    cudaFuncSetAttribute(gemm_tf32_db,
                         cudaFuncAttributeMaxDynamicSharedMemorySize, GEMM_SMEM_BYTES);
    cudaFuncSetAttribute(space_attn_mma,
                         cudaFuncAttributeMaxDynamicSharedMemorySize, SAT_SMEM_BYTES);

    static cudaStream_t s2 = nullptr;
    static cudaEvent_t e_fork = nullptr, e_prep = nullptr, e_qkv = nullptr, e_cls = nullptr;
    if (!s2) {
        cudaStreamCreateWithFlags(&s2, cudaStreamNonBlocking);
        cudaEventCreateWithFlags(&e_fork, cudaEventDisableTiming);
        cudaEventCreateWithFlags(&e_prep, cudaEventDisableTiming);
        cudaEventCreateWithFlags(&e_qkv,  cudaEventDisableTiming);
        cudaEventCreateWithFlags(&e_cls,  cudaEventDisableTiming);
    }

    // ---- fork s2 from the (captured) default stream ----
    cudaEventRecord(e_fork, 0);
    cudaStreamWaitEvent(s2, e_fork, 0);

    // s2: weight prep for q2/U/proj (independent of qkv)
    round_tf32_kernel<<<(C_*C_/4 + 255)/256, 256, 0, s2>>>(W_pq,   wpqr,   C_*C_);
    round_tf32_kernel<<<(C_*C_/4 + 255)/256, 256, 0, s2>>>(W_proj, wprojr, C_*C_);
    transpose_round_kernel<<<dim3(C_/32, C_/32), dim3(32, 8), 0, s2>>>(W_pkv, wkT);
    cudaEventRecord(e_prep, s2);

    // main: x + Wqkv prep, qkv GEMM
    round_tf32_kernel<<<(B_*N_*C_/4 + 255)/256, 256>>>(x,     xr,    B_*N_*C_);
    round_tf32_kernel<<<(C_*C3_ /4 + 255)/256, 256>>>(W_qkv, wqkvr, C_*C3_);
    gemm_tf32_db<<<dim3(C3_/128, (B_*N_ + 127)/128), 256, GEMM_SMEM_BYTES>>>(
        xr, C_, wqkvr, C3_, qkv, C3_, B_*N_, C_, 1.f, nullptr, 0, 0, 0, 0);
    cudaEventRecord(e_qkv, 0);

    // s2: cls attention (needs qkv)
    cudaStreamWaitEvent(s2, e_qkv, 0);
    cls_attn_kernel<<<B_ * H_, 256, 0, s2>>>();
    cudaEventRecord(e_cls, s2);

    // main: space attention -> traj
    space_attn_mma<<<dim3(13, F_, B_ * H_), 256, SAT_SMEM_BYTES>>>();

    // main: q2 (needs wpqr from s2)
    cudaStreamWaitEvent(0, e_prep, 0);
    gemm_tf32_db<<<dim3(C_/128, (BS_ + 127)/128), 256, GEMM_SMEM_BYTES>>>(
        traj, 0, wpqr, C_, q2, C_, BS_, C_, SCALE, nullptr, 1 | 2, 0, 0, 0);

    // main: U_h = Q2_h @ WkT_h -> u[bs][h*C+c]  (zsc = column offset C_)
    gemm_tf32_db<<<dim3(C_/128, (BS_ + 127)/128, H_), 256, GEMM_SMEM_BYTES>>>(
        q2, C_, wkT, C_, u, H_ * C_, BS_, D_, 1.f, nullptr, 0,
        D_, (size_t)D_ * C_, (size_t)C_);

    // main: frame logits + softmax + weighted traj sum
    final_attn2_kernel<<<BS_, 256>>>(attn);

    // join: proj needs cls rows from s2
    cudaStreamWaitEvent(0, e_cls, 0);
    gemm_tf32_db<<<dim3(C_/128, (B_*N_ + 127)/128), 256, GEMM_SMEM_BYTES>>>(
        attin, C_, wprojr, C_, out, C_, B_*N_, C_, 1.f, b_proj, 0, 0, 0, 0);
}